// round 3
// baseline (speedup 1.0000x reference)
#include <cuda_runtime.h>
#include <math.h>

#define BB   4
#define NN   4096
#define FIN  256
#define FF   128
#define NT   32      // query rows per block (kernel 2)
#define MT   64      // key tile (kernel 2)
#define LRA  0.2f

typedef unsigned long long ull;

// Scratch (device globals: allocation-free rule)
__device__ float g_Wh [BB * NN * FF];   // 8 MB
__device__ float g_Wh1[BB * NN];
__device__ float g_Wh2[BB * NN];

// ---- packed fp32x2 helpers (B300 2x fp32 path; only reachable via PTX) ----
__device__ __forceinline__ ull ffma2(ull a, ull b, ull c) {
    ull d;
    asm("fma.rn.f32x2 %0, %1, %2, %3;" : "=l"(d) : "l"(a), "l"(b), "l"(c));
    return d;
}
__device__ __forceinline__ ull pack2(float x) {
    ull p;
    asm("mov.b64 %0, {%1, %2};" : "=l"(p) : "f"(x), "f"(x));
    return p;
}
__device__ __forceinline__ float2 unpack2(ull p) {
    float lo, hi;
    asm("mov.b64 {%0, %1}, %2;" : "=f"(lo), "=f"(hi) : "l"(p));
    return make_float2(lo, hi);
}

// ============================================================================
// Kernel 1: Wh = h @ W  (16384x128, K=256), fused Wh1 = Wh@a1, Wh2 = Wh@a2.
// 16 rows/block, 128 threads; micro-tile 4 rows x 4 cols per thread.
// One warp owns 4 full rows -> Wh1/Wh2 via in-warp reduction (no extra kernel).
// ============================================================================
__global__ void k_wh(const float* __restrict__ h,
                     const float* __restrict__ W,
                     const float* __restrict__ av) {
    __shared__ float sh[16 * FIN];     // 16 KB h tile
    __shared__ float sa[2 * FF];       // a1 | a2

    const int t    = threadIdx.x;
    const int row0 = blockIdx.x * 16;

    const float4* src = (const float4*)(h + (size_t)row0 * FIN);
    #pragma unroll
    for (int i = 0; i < 8; i++) ((float4*)sh)[t + i * 128] = src[t + i * 128];
    if (t < 64) ((float4*)sa)[t] = ((const float4*)av)[t];
    __syncthreads();

    const int rg = t >> 5, cg = t & 31;
    const int c0 = cg * 4;

    float acc[4][4];
    #pragma unroll
    for (int i = 0; i < 4; i++)
        #pragma unroll
        for (int j = 0; j < 4; j++) acc[i][j] = 0.f;

    #pragma unroll 4
    for (int k = 0; k < FIN; k++) {
        const float4 w4 = *(const float4*)(W + (size_t)k * FF + c0);
        #pragma unroll
        for (int i = 0; i < 4; i++) {
            const float a_ = sh[(rg * 4 + i) * FIN + k];
            acc[i][0] += a_ * w4.x;
            acc[i][1] += a_ * w4.y;
            acc[i][2] += a_ * w4.z;
            acc[i][3] += a_ * w4.w;
        }
    }

    #pragma unroll
    for (int i = 0; i < 4; i++) {
        const int row = row0 + rg * 4 + i;
        *(float4*)&g_Wh[(size_t)row * FF + c0] =
            make_float4(acc[i][0], acc[i][1], acc[i][2], acc[i][3]);

        float p1 = acc[i][0] * sa[c0]        + acc[i][1] * sa[c0 + 1]
                 + acc[i][2] * sa[c0 + 2]    + acc[i][3] * sa[c0 + 3];
        float p2 = acc[i][0] * sa[FF + c0]   + acc[i][1] * sa[FF + c0 + 1]
                 + acc[i][2] * sa[FF + c0 + 2] + acc[i][3] * sa[FF + c0 + 3];
        #pragma unroll
        for (int off = 16; off; off >>= 1) {
            p1 += __shfl_xor_sync(0xffffffffu, p1, off);
            p2 += __shfl_xor_sync(0xffffffffu, p2, off);
        }
        if (cg == 0) { g_Wh1[row] = p1; g_Wh2[row] = p2; }
    }
}

// ============================================================================
// Kernel 2: fused masked-softmax attention + (P @ Wh)/rowsum + ELU.
// Scores are bounded (|Wh1|,|Wh2| small) => no max-subtraction needed;
// P[n,m] = adj ? exp(lrelu(Wh1[n]+Wh2[m])) : 0 computed tile-by-tile into
// SMEM, stored PRE-DUPLICATED as f32x2 pairs so the GEMM needs no packs.
// 32 rows x full-F accumulators; 64-key tiles; f32x2 FMA mainloop.
// ============================================================================
#define S_P2   (NT * MT * 8)                 // 16384 B  : P tile, duplicated pairs
#define S_WHT  (MT * FF * 4)                 // 32768 B  : Wh tile [MT][FF]
#define SMEM2  (S_P2 + S_WHT + NT * 4 + MT * 4 + NT * 4)   // 49664 B

__global__ void k_attn(const int* __restrict__ adj, float* __restrict__ out) {
    extern __shared__ char smem[];
    ull*   sP2  = (ull*)smem;                         // [NT][MT]
    float* sWhT = (float*)(smem + S_P2);              // [MT][FF]
    float* sWh1 = (float*)(smem + S_P2 + S_WHT);      // [NT]
    float* sWh2 = sWh1 + NT;                          // [MT]
    float* sDen = sWh2 + MT;                          // [NT]

    const int t  = threadIdx.x;
    const int b  = blockIdx.x >> 7;
    const int n0 = (blockIdx.x & 127) * NT;
    const int rg = t >> 5, cg = t & 31;

    if (t < NT) { sWh1[t] = g_Wh1[b * NN + n0 + t]; sDen[t] = 0.f; }

    ull acc[4][2];
    #pragma unroll
    for (int i = 0; i < 4; i++) { acc[i][0] = 0ull; acc[i][1] = 0ull; }

    const float* whBatch = g_Wh + (size_t)b * NN * FF;
    const int*   adjBase = adj + ((size_t)b * NN + n0) * NN;

    for (int mt = 0; mt < NN; mt += MT) {
        __syncthreads();   // previous tile's sP2/sWhT fully consumed

        // ---- Phase A: stage Wh tile (contiguous 64 rows) + Wh2 slice ----
        {
            const float4* s4 = (const float4*)(whBatch + (size_t)mt * FF);
            float4*       d4 = (float4*)sWhT;
            #pragma unroll
            for (int i = 0; i < 8; i++) d4[t + i * 256] = s4[t + i * 256];
            if (t < MT / 4)
                ((float4*)sWh2)[t] = *(const float4*)(g_Wh2 + b * NN + mt + t * 4);
        }
        __syncthreads();

        // ---- Phase B: P tile + row-sum (half-warp groups share a row) ----
        #pragma unroll
        for (int it = 0; it < 2; it++) {
            const int q   = it * 256 + t;
            const int row = q >> 4;             // 16 int4 per 64-wide row
            const int c4  = (q & 15) << 2;
            const int4 avj = __ldg((const int4*)(adjBase + (size_t)row * NN + mt + c4));
            const float w1v = sWh1[row];

            float s0 = w1v + sWh2[c4 + 0]; s0 = (s0 >= 0.f) ? s0 : LRA * s0;
            float s1 = w1v + sWh2[c4 + 1]; s1 = (s1 >= 0.f) ? s1 : LRA * s1;
            float s2 = w1v + sWh2[c4 + 2]; s2 = (s2 >= 0.f) ? s2 : LRA * s2;
            float s3 = w1v + sWh2[c4 + 3]; s3 = (s3 >= 0.f) ? s3 : LRA * s3;

            const float p0 = (avj.x > 0) ? __expf(s0) : 0.f;
            const float p1 = (avj.y > 0) ? __expf(s1) : 0.f;
            const float p2 = (avj.z > 0) ? __expf(s2) : 0.f;
            const float p3 = (avj.w > 0) ? __expf(s3) : 0.f;

            ulonglong2 st0; st0.x = pack2(p0); st0.y = pack2(p1);
            ulonglong2 st1; st1.x = pack2(p2); st1.y = pack2(p3);
            *(ulonglong2*)&sP2[row * MT + c4]     = st0;
            *(ulonglong2*)&sP2[row * MT + c4 + 2] = st1;

            float ps = (p0 + p1) + (p2 + p3);
            ps += __shfl_xor_sync(0xffffffffu, ps, 1);
            ps += __shfl_xor_sync(0xffffffffu, ps, 2);
            ps += __shfl_xor_sync(0xffffffffu, ps, 4);
            ps += __shfl_xor_sync(0xffffffffu, ps, 8);
            if ((t & 15) == 0) atomicAdd(&sDen[row], ps);
        }
        __syncthreads();

        // ---- Phase C: acc += P[32xMT] @ Wh[MTx128], f32x2 mainloop ----
        // Per warp: a-loads are broadcast (same row), w-loads 512B contiguous.
        const ull*   aBase = sP2 + (rg * 4) * MT;
        const float* wBase = sWhT + cg * 4;
        #pragma unroll 8
        for (int kk = 0; kk < MT; kk += 2) {
            const ulonglong2 wk  = *(const ulonglong2*)(wBase + (size_t)kk * FF);
            const ulonglong2 wk1 = *(const ulonglong2*)(wBase + (size_t)(kk + 1) * FF);
            #pragma unroll
            for (int i = 0; i < 4; i++) {
                const ulonglong2 ap = *(const ulonglong2*)(aBase + i * MT + kk);
                acc[i][0] = ffma2(ap.x, wk.x,  acc[i][0]);
                acc[i][1] = ffma2(ap.x, wk.y,  acc[i][1]);
                acc[i][0] = ffma2(ap.y, wk1.x, acc[i][0]);
                acc[i][1] = ffma2(ap.y, wk1.y, acc[i][1]);
            }
        }
    }
    __syncthreads();

    // ---- Epilogue: normalize + ELU, coalesced float4 stores ----
    #pragma unroll
    for (int i = 0; i < 4; i++) {
        const int  row = n0 + rg * 4 + i;
        const float inv = 1.0f / sDen[rg * 4 + i];
        const float2 v0 = unpack2(acc[i][0]);
        const float2 v1 = unpack2(acc[i][1]);
        float o0 = v0.x * inv, o1 = v0.y * inv, o2 = v1.x * inv, o3 = v1.y * inv;
        o0 = (o0 > 0.f) ? o0 : expm1f(o0);
        o1 = (o1 > 0.f) ? o1 : expm1f(o1);
        o2 = (o2 > 0.f) ? o2 : expm1f(o2);
        o3 = (o3 > 0.f) ? o3 : expm1f(o3);
        *(float4*)&out[((size_t)b * NN + row) * FF + cg * 4] =
            make_float4(o0, o1, o2, o3);
    }
}

// ============================================================================
extern "C" void kernel_launch(void* const* d_in, const int* in_sizes, int n_in,
                              void* d_out, int out_size) {
    const float* h   = (const float*)d_in[0];
    const int*   adj = (const int*)  d_in[1];
    const float* W   = (const float*)d_in[2];
    const float* av  = (const float*)d_in[3];
    float*       out = (float*)d_out;

    k_wh<<<(BB * NN) / 16, 128>>>(h, W, av);

    cudaFuncSetAttribute(k_attn, cudaFuncAttributeMaxDynamicSharedMemorySize, SMEM2);
    k_attn<<<BB * (NN / NT), 256, SMEM2>>>(adj, out);
}

// round 5
// speedup vs baseline: 2.1336x; 2.1336x over previous
#include <cuda_runtime.h>
#include <math.h>
#include <stdint.h>

#define BB   4
#define NN   4096
#define FIN  256
#define FF   128
#define QT   128               // query rows per block (k_attn)
#define KT   64                // key tile
#define ITERS (NN / KT)
#define PSTR 68                // padded stride (words) of P tile  -> conflict-free frags
#define BSTR 136               // padded stride (words) of Wh tile -> conflict-free frags
#define LRA  0.2f

// Scratch (device globals: allocation-free rule)
__device__ float g_Wh [BB * NN * FF];   // 8 MB, tf32-rounded Wh (B operand)
__device__ float g_Wh1[BB * NN];
__device__ float g_Wh2[BB * NN];

// ---------------------------------------------------------------------------
__device__ __forceinline__ uint32_t cvt_tf32(float x) {
    uint32_t u;
    asm("cvt.rna.tf32.f32 %0, %1;" : "=r"(u) : "f"(x));
    return u;
}
__device__ __forceinline__ void mma_tf32(float* c, const uint32_t* a, const uint32_t* b) {
    asm volatile(
        "mma.sync.aligned.m16n8k8.row.col.f32.tf32.tf32.f32 "
        "{%0,%1,%2,%3}, {%4,%5,%6,%7}, {%8,%9}, {%0,%1,%2,%3};"
        : "+f"(c[0]), "+f"(c[1]), "+f"(c[2]), "+f"(c[3])
        : "r"(a[0]), "r"(a[1]), "r"(a[2]), "r"(a[3]), "r"(b[0]), "r"(b[1]));
}
__device__ __forceinline__ uint32_t smem_u32(const void* p) {
    uint32_t a;
    asm("{ .reg .u64 t; cvta.to.shared.u64 t, %1; cvt.u32.u64 %0, t; }"
        : "=r"(a) : "l"(p));
    return a;
}
__device__ __forceinline__ void cp16(uint32_t dst, const void* src) {
    asm volatile("cp.async.cg.shared.global [%0], [%1], 16;" :: "r"(dst), "l"(src));
}

// ============================================================================
// Kernel 1: Wh = h @ W (tf32-rounded at store), fused Wh1/Wh2 (full fp32).
// ============================================================================
__global__ void k_wh(const float* __restrict__ h,
                     const float* __restrict__ W,
                     const float* __restrict__ av) {
    __shared__ float sh[16 * FIN];
    __shared__ float sa[2 * FF];

    const int t    = threadIdx.x;
    const int row0 = blockIdx.x * 16;

    const float4* src = (const float4*)(h + (size_t)row0 * FIN);
    #pragma unroll
    for (int i = 0; i < 8; i++) ((float4*)sh)[t + i * 128] = src[t + i * 128];
    if (t < 64) ((float4*)sa)[t] = ((const float4*)av)[t];
    __syncthreads();

    const int rg = t >> 5, cg = t & 31;
    const int c0 = cg * 4;

    float acc[4][4];
    #pragma unroll
    for (int i = 0; i < 4; i++)
        #pragma unroll
        for (int j = 0; j < 4; j++) acc[i][j] = 0.f;

    #pragma unroll 4
    for (int k = 0; k < FIN; k++) {
        const float4 w4 = *(const float4*)(W + (size_t)k * FF + c0);
        #pragma unroll
        for (int i = 0; i < 4; i++) {
            const float a_ = sh[(rg * 4 + i) * FIN + k];
            acc[i][0] += a_ * w4.x;
            acc[i][1] += a_ * w4.y;
            acc[i][2] += a_ * w4.z;
            acc[i][3] += a_ * w4.w;
        }
    }

    #pragma unroll
    for (int i = 0; i < 4; i++) {
        const int row = row0 + rg * 4 + i;

        // store Wh pre-rounded to tf32 (B operand of the mma)
        uint4 uv;
        uv.x = cvt_tf32(acc[i][0]);
        uv.y = cvt_tf32(acc[i][1]);
        uv.z = cvt_tf32(acc[i][2]);
        uv.w = cvt_tf32(acc[i][3]);
        *(uint4*)&g_Wh[(size_t)row * FF + c0] = uv;

        // Wh1/Wh2 from full-precision acc
        float p1 = acc[i][0] * sa[c0]          + acc[i][1] * sa[c0 + 1]
                 + acc[i][2] * sa[c0 + 2]      + acc[i][3] * sa[c0 + 3];
        float p2 = acc[i][0] * sa[FF + c0]     + acc[i][1] * sa[FF + c0 + 1]
                 + acc[i][2] * sa[FF + c0 + 2] + acc[i][3] * sa[FF + c0 + 3];
        #pragma unroll
        for (int off = 16; off; off >>= 1) {
            p1 += __shfl_xor_sync(0xffffffffu, p1, off);
            p2 += __shfl_xor_sync(0xffffffffu, p2, off);
        }
        if (cg == 0) { g_Wh1[row] = p1; g_Wh2[row] = p2; }
    }
}

// ============================================================================
// Kernel 2: fused masked-softmax attention, tensor pipe via mma.sync tf32.
// Block: 128 q-rows x 128 cols, register accumulators (8 warps x 32x64).
// Per KT=64 tile: phase B computes P (exp, no-max: scores bounded) into SMEM;
// Wh tile double-buffered via cp.async; adj prefetched in regs; phase C runs
// m16n8k8 tf32 mma. Denominator = running exp-sum of tf32-rounded P.
// ============================================================================
#define OFF_SB0 (QT * PSTR * 4)                  // 34816
#define OFF_SB1 (OFF_SB0 + KT * BSTR * 4)        // 69632
#define OFF_DEN (OFF_SB1 + KT * BSTR * 4)        // 104448
#define SMEM_DYN (OFF_DEN + QT * 4)              // 104960

__global__ void __launch_bounds__(256, 1)
k_attn(const int* __restrict__ adj, float* __restrict__ out) {
    extern __shared__ char sm[];
    uint32_t* sA = (uint32_t*)sm;                // P tile [QT][PSTR] (tf32 bits)
    const uint32_t sbase = smem_u32(sm);

    const int t = threadIdx.x, lane = t & 31, wid = t >> 5;
    const int b = blockIdx.x >> 5;
    const int n0 = (blockIdx.x & 31) * QT;

    // phase-B geometry: thread owns (row = t>>1, 32 cols at half)
    const int prow = t >> 1;
    const int pcol = (t & 1) * 32;
    const float w1 = __ldg(&g_Wh1[b * NN + n0 + prow]);
    const int*   adjP = adj + ((size_t)(b * NN + n0 + prow)) * NN + pcol;
    const float* wh2P = g_Wh2 + b * NN + pcol;
    const float* whS  = g_Wh + (size_t)b * NN * FF;

    // cp.async Wh-tile stage: 2048 float4 chunks, 8 per thread
    auto cp_tile = [&](int mt, uint32_t bufOff) {
        #pragma unroll
        for (int i = 0; i < 8; i++) {
            const int q = t + i * 256;
            const int r = q >> 5, c4 = q & 31;
            cp16(sbase + bufOff + (uint32_t)(r * BSTR + c4 * 4) * 4,
                 whS + (size_t)(mt + r) * FF + c4 * 4);
        }
        asm volatile("cp.async.commit_group;" ::: "memory");
    };

    // preload tile 0
    int4 adjR[8];
    #pragma unroll
    for (int j = 0; j < 8; j++) adjR[j] = __ldg((const int4*)adjP + j);
    cp_tile(0, OFF_SB0);

    float acc[2][8][4];
    #pragma unroll
    for (int mi = 0; mi < 2; mi++)
        #pragma unroll
        for (int ni = 0; ni < 8; ni++)
            #pragma unroll
            for (int q = 0; q < 4; q++) acc[mi][ni][q] = 0.f;

    float den = 0.f;
    const int g = lane >> 2, tig = lane & 3;
    const int m0 = (wid & 3) * 32, nb0 = (wid >> 2) * 64;

    for (int it = 0; it < ITERS; ++it) {
        const int mt = it * KT;
        const uint32_t bOff = (it & 1) ? OFF_SB1 : OFF_SB0;

        __syncthreads();                              // prev mma done with sA
        asm volatile("cp.async.wait_group 0;" ::: "memory");

        // ---- phase B: P tile (masked exp, tf32-rounded) ----
        #pragma unroll
        for (int j = 0; j < 8; j++) {
            const float4 w2 = __ldg((const float4*)(wh2P + mt) + j);
            float s0 = w1 + w2.x; s0 = fmaxf(s0, LRA * s0);
            float s1 = w1 + w2.y; s1 = fmaxf(s1, LRA * s1);
            float s2 = w1 + w2.z; s2 = fmaxf(s2, LRA * s2);
            float s3 = w1 + w2.w; s3 = fmaxf(s3, LRA * s3);
            uint4 pv;
            pv.x = cvt_tf32((adjR[j].x > 0) ? __expf(s0) : 0.f);
            pv.y = cvt_tf32((adjR[j].y > 0) ? __expf(s1) : 0.f);
            pv.z = cvt_tf32((adjR[j].z > 0) ? __expf(s2) : 0.f);
            pv.w = cvt_tf32((adjR[j].w > 0) ? __expf(s3) : 0.f);
            den += (__uint_as_float(pv.x) + __uint_as_float(pv.y))
                 + (__uint_as_float(pv.z) + __uint_as_float(pv.w));
            *(uint4*)(sA + prow * PSTR + pcol + 4 * j) = pv;
        }
        __syncthreads();                              // sA + sB[buf] visible

        // ---- prefetch next tile (adj regs + cp.async Wh) ----
        if (it + 1 < ITERS) {
            #pragma unroll
            for (int j = 0; j < 8; j++)
                adjR[j] = __ldg((const int4*)(adjP + mt + KT) + j);
            cp_tile(mt + KT, (it & 1) ? OFF_SB0 : OFF_SB1);
        }

        // ---- phase C: acc += P[128xKT] @ Wh[KTx128] on tensor pipe ----
        const uint32_t* B = (const uint32_t*)(sm + bOff);
        #pragma unroll 2
        for (int ks = 0; ks < 8; ++ks) {
            const int k0 = ks * 8;
            uint32_t af[2][4];
            #pragma unroll
            for (int mi = 0; mi < 2; mi++) {
                const uint32_t* ap = sA + (m0 + 16 * mi + g) * PSTR + k0 + tig;
                af[mi][0] = ap[0];
                af[mi][1] = ap[8 * PSTR];
                af[mi][2] = ap[4];
                af[mi][3] = ap[8 * PSTR + 4];
            }
            uint32_t bf[8][2];
            #pragma unroll
            for (int ni = 0; ni < 8; ni++) {
                const uint32_t* bp = B + (k0 + tig) * BSTR + nb0 + 8 * ni + g;
                bf[ni][0] = bp[0];
                bf[ni][1] = bp[4 * BSTR];
            }
            #pragma unroll
            for (int mi = 0; mi < 2; mi++)
                #pragma unroll
                for (int ni = 0; ni < 8; ni++)
                    mma_tf32(acc[mi][ni], af[mi], bf[ni]);
        }
    }

    // ---- denominator: pair-reduce (t, t^1 share a row) ----
    float* sDen = (float*)(sm + OFF_DEN);
    const float dsum = den + __shfl_xor_sync(0xffffffffu, den, 1);
    if ((t & 1) == 0) sDen[prow] = dsum;
    __syncthreads();

    // ---- epilogue: normalize + ELU, float2 stores ----
    #pragma unroll
    for (int mi = 0; mi < 2; mi++) {
        const int rloc = m0 + 16 * mi + g;
        const int r0 = n0 + rloc;
        const float i0 = 1.0f / sDen[rloc];
        const float i1 = 1.0f / sDen[rloc + 8];
        #pragma unroll
        for (int ni = 0; ni < 8; ni++) {
            const int col = nb0 + 8 * ni + 2 * tig;
            float o0 = acc[mi][ni][0] * i0, o1 = acc[mi][ni][1] * i0;
            float o2 = acc[mi][ni][2] * i1, o3 = acc[mi][ni][3] * i1;
            o0 = (o0 > 0.f) ? o0 : expm1f(o0);
            o1 = (o1 > 0.f) ? o1 : expm1f(o1);
            o2 = (o2 > 0.f) ? o2 : expm1f(o2);
            o3 = (o3 > 0.f) ? o3 : expm1f(o3);
            float2 v0 = make_float2(o0, o1);
            float2 v1 = make_float2(o2, o3);
            *(float2*)&out[((size_t)(b * NN) + r0)     * FF + col] = v0;
            *(float2*)&out[((size_t)(b * NN) + r0 + 8) * FF + col] = v1;
        }
    }
}

// ============================================================================
extern "C" void kernel_launch(void* const* d_in, const int* in_sizes, int n_in,
                              void* d_out, int out_size) {
    const float* h   = (const float*)d_in[0];
    const int*   adj = (const int*)  d_in[1];
    const float* W   = (const float*)d_in[2];
    const float* av  = (const float*)d_in[3];
    float*       out = (float*)d_out;

    k_wh<<<(BB * NN) / 16, 128>>>(h, W, av);

    cudaFuncSetAttribute(k_attn, cudaFuncAttributeMaxDynamicSharedMemorySize, SMEM_DYN);
    k_attn<<<BB * (NN / QT), 256, SMEM_DYN>>>(adj, out);
}

// round 6
// speedup vs baseline: 2.7120x; 1.2711x over previous
#include <cuda_runtime.h>
#include <math.h>
#include <stdint.h>

#define BB   4
#define NN   4096
#define FIN  256
#define FF   128
#define QT   64                // query rows per block (k_attn)
#define KT   64                // key tile
#define ITERS (NN / KT)
#define PSTR 68                // padded stride (words) of P tile  -> conflict-free frags
#define BSTR 136               // padded stride (words) of Wh tile -> conflict-free frags
#define LRA  0.2f

// Scratch (device globals: allocation-free rule)
__device__ float g_Wh [BB * NN * FF];   // 8 MB, tf32-rounded Wh (B operand)
__device__ float g_Wh1[BB * NN];
__device__ float g_Wh2[BB * NN];

// ---------------------------------------------------------------------------
__device__ __forceinline__ uint32_t cvt_tf32(float x) {
    uint32_t u;
    asm("cvt.rna.tf32.f32 %0, %1;" : "=r"(u) : "f"(x));
    return u;
}
__device__ __forceinline__ void mma_tf32(float* c, const uint32_t* a, const uint32_t* b) {
    asm volatile(
        "mma.sync.aligned.m16n8k8.row.col.f32.tf32.tf32.f32 "
        "{%0,%1,%2,%3}, {%4,%5,%6,%7}, {%8,%9}, {%0,%1,%2,%3};"
        : "+f"(c[0]), "+f"(c[1]), "+f"(c[2]), "+f"(c[3])
        : "r"(a[0]), "r"(a[1]), "r"(a[2]), "r"(a[3]), "r"(b[0]), "r"(b[1]));
}
__device__ __forceinline__ uint32_t smem_u32(const void* p) {
    uint32_t a;
    asm("{ .reg .u64 t; cvta.to.shared.u64 t, %1; cvt.u32.u64 %0, t; }"
        : "=r"(a) : "l"(p));
    return a;
}
__device__ __forceinline__ void cp16(uint32_t dst, const void* src) {
    asm volatile("cp.async.cg.shared.global [%0], [%1], 16;" :: "r"(dst), "l"(src));
}

// ============================================================================
// Kernel 1: Wh = h @ W (tf32-rounded at store), fused Wh1/Wh2 (full fp32).
// ============================================================================
__global__ void k_wh(const float* __restrict__ h,
                     const float* __restrict__ W,
                     const float* __restrict__ av) {
    __shared__ float sh[16 * FIN];
    __shared__ float sa[2 * FF];

    const int t    = threadIdx.x;
    const int row0 = blockIdx.x * 16;

    const float4* src = (const float4*)(h + (size_t)row0 * FIN);
    #pragma unroll
    for (int i = 0; i < 8; i++) ((float4*)sh)[t + i * 128] = src[t + i * 128];
    if (t < 64) ((float4*)sa)[t] = ((const float4*)av)[t];
    __syncthreads();

    const int rg = t >> 5, cg = t & 31;
    const int c0 = cg * 4;

    float acc[4][4];
    #pragma unroll
    for (int i = 0; i < 4; i++)
        #pragma unroll
        for (int j = 0; j < 4; j++) acc[i][j] = 0.f;

    #pragma unroll 4
    for (int k = 0; k < FIN; k++) {
        const float4 w4 = *(const float4*)(W + (size_t)k * FF + c0);
        #pragma unroll
        for (int i = 0; i < 4; i++) {
            const float a_ = sh[(rg * 4 + i) * FIN + k];
            acc[i][0] += a_ * w4.x;
            acc[i][1] += a_ * w4.y;
            acc[i][2] += a_ * w4.z;
            acc[i][3] += a_ * w4.w;
        }
    }

    #pragma unroll
    for (int i = 0; i < 4; i++) {
        const int row = row0 + rg * 4 + i;

        // store Wh pre-rounded to tf32 (B operand of the mma)
        uint4 uv;
        uv.x = cvt_tf32(acc[i][0]);
        uv.y = cvt_tf32(acc[i][1]);
        uv.z = cvt_tf32(acc[i][2]);
        uv.w = cvt_tf32(acc[i][3]);
        *(uint4*)&g_Wh[(size_t)row * FF + c0] = uv;

        // Wh1/Wh2 from full-precision acc
        float p1 = acc[i][0] * sa[c0]          + acc[i][1] * sa[c0 + 1]
                 + acc[i][2] * sa[c0 + 2]      + acc[i][3] * sa[c0 + 3];
        float p2 = acc[i][0] * sa[FF + c0]     + acc[i][1] * sa[FF + c0 + 1]
                 + acc[i][2] * sa[FF + c0 + 2] + acc[i][3] * sa[FF + c0 + 3];
        #pragma unroll
        for (int off = 16; off; off >>= 1) {
            p1 += __shfl_xor_sync(0xffffffffu, p1, off);
            p2 += __shfl_xor_sync(0xffffffffu, p2, off);
        }
        if (cg == 0) { g_Wh1[row] = p1; g_Wh2[row] = p2; }
    }
}

// ============================================================================
// Kernel 2: fused masked-softmax attention on tensor pipe (mma.sync tf32).
// QT=64 rows/CTA, 2 CTAs/SM (cross-CTA phase overlap: one CTA's exp phase
// hides the sibling's MMA phase). 8 warps: m0 = (wid&1)*32, nb0 = (wid>>1)*32.
// Per KT=64 tile: phase B computes P (masked exp, no-max: scores bounded)
// into SMEM; Wh tile double-buffered via cp.async; adj prefetched in regs.
// ============================================================================
#define OFF_SB0 (QT * PSTR * 4)                  // 17408
#define OFF_SB1 (OFF_SB0 + KT * BSTR * 4)        // 52224
#define OFF_DEN (OFF_SB1 + KT * BSTR * 4)        // 87040
#define SMEM_DYN (OFF_DEN + QT * 4)              // 87296

__global__ void __launch_bounds__(256, 2)
k_attn(const int* __restrict__ adj, float* __restrict__ out) {
    extern __shared__ char sm[];
    uint32_t* sA = (uint32_t*)sm;                // P tile [QT][PSTR] (tf32 bits)
    const uint32_t sbase = smem_u32(sm);

    const int t = threadIdx.x, lane = t & 31, wid = t >> 5;
    const int b = blockIdx.x >> 6;
    const int n0 = (blockIdx.x & 63) * QT;

    // phase-B geometry: 4 threads per row, 16 cols each
    const int prow = t >> 2;
    const int pcol = (t & 3) * 16;
    const float w1 = __ldg(&g_Wh1[b * NN + n0 + prow]);
    const int*   adjP = adj + ((size_t)(b * NN + n0 + prow)) * NN + pcol;
    const float* wh2P = g_Wh2 + b * NN + pcol;
    const float* whS  = g_Wh + (size_t)b * NN * FF;

    // cp.async Wh-tile stage: 2048 float4 chunks, 8 per thread
    auto cp_tile = [&](int mt, uint32_t bufOff) {
        #pragma unroll
        for (int i = 0; i < 8; i++) {
            const int q = t + i * 256;
            const int r = q >> 5, c4 = q & 31;
            cp16(sbase + bufOff + (uint32_t)(r * BSTR + c4 * 4) * 4,
                 whS + (size_t)(mt + r) * FF + c4 * 4);
        }
        asm volatile("cp.async.commit_group;" ::: "memory");
    };

    // preload tile 0
    int4 adjR[4];
    #pragma unroll
    for (int j = 0; j < 4; j++) adjR[j] = __ldg((const int4*)adjP + j);
    cp_tile(0, OFF_SB0);

    float acc[2][4][4];
    #pragma unroll
    for (int mi = 0; mi < 2; mi++)
        #pragma unroll
        for (int ni = 0; ni < 4; ni++)
            #pragma unroll
            for (int q = 0; q < 4; q++) acc[mi][ni][q] = 0.f;

    float den = 0.f;
    const int g = lane >> 2, tig = lane & 3;
    const int m0 = (wid & 1) * 32, nb0 = (wid >> 1) * 32;

    for (int it = 0; it < ITERS; ++it) {
        const int mt = it * KT;
        const uint32_t bOff = (it & 1) ? OFF_SB1 : OFF_SB0;

        __syncthreads();                              // prev mma done with sA
        asm volatile("cp.async.wait_group 0;" ::: "memory");

        // ---- phase B: P tile (masked exp, tf32-rounded) ----
        #pragma unroll
        for (int j = 0; j < 4; j++) {
            const float4 w2 = __ldg((const float4*)(wh2P + mt) + j);
            float s0 = w1 + w2.x; s0 = fmaxf(s0, LRA * s0);
            float s1 = w1 + w2.y; s1 = fmaxf(s1, LRA * s1);
            float s2 = w1 + w2.z; s2 = fmaxf(s2, LRA * s2);
            float s3 = w1 + w2.w; s3 = fmaxf(s3, LRA * s3);
            uint4 pv;
            pv.x = cvt_tf32((adjR[j].x > 0) ? __expf(s0) : 0.f);
            pv.y = cvt_tf32((adjR[j].y > 0) ? __expf(s1) : 0.f);
            pv.z = cvt_tf32((adjR[j].z > 0) ? __expf(s2) : 0.f);
            pv.w = cvt_tf32((adjR[j].w > 0) ? __expf(s3) : 0.f);
            den += (__uint_as_float(pv.x) + __uint_as_float(pv.y))
                 + (__uint_as_float(pv.z) + __uint_as_float(pv.w));
            *(uint4*)(sA + prow * PSTR + pcol + 4 * j) = pv;
        }
        __syncthreads();                              // sA + sB[buf] visible

        // ---- prefetch next tile (adj regs + cp.async Wh) ----
        if (it + 1 < ITERS) {
            #pragma unroll
            for (int j = 0; j < 4; j++)
                adjR[j] = __ldg((const int4*)(adjP + mt + KT) + j);
            cp_tile(mt + KT, (it & 1) ? OFF_SB0 : OFF_SB1);
        }

        // ---- phase C: acc += P[QTxKT] @ Wh[KTx128] on tensor pipe ----
        const uint32_t* B = (const uint32_t*)(sm + bOff);
        #pragma unroll 2
        for (int ks = 0; ks < 8; ++ks) {
            const int k0 = ks * 8;
            uint32_t af[2][4];
            #pragma unroll
            for (int mi = 0; mi < 2; mi++) {
                const uint32_t* ap = sA + (m0 + 16 * mi + g) * PSTR + k0 + tig;
                af[mi][0] = ap[0];
                af[mi][1] = ap[8 * PSTR];
                af[mi][2] = ap[4];
                af[mi][3] = ap[8 * PSTR + 4];
            }
            uint32_t bf[4][2];
            #pragma unroll
            for (int ni = 0; ni < 4; ni++) {
                const uint32_t* bp = B + (k0 + tig) * BSTR + nb0 + 8 * ni + g;
                bf[ni][0] = bp[0];
                bf[ni][1] = bp[4 * BSTR];
            }
            #pragma unroll
            for (int mi = 0; mi < 2; mi++)
                #pragma unroll
                for (int ni = 0; ni < 4; ni++)
                    mma_tf32(acc[mi][ni], af[mi], bf[ni]);
        }
    }

    // ---- denominator: reduce across the 4 threads sharing a row ----
    float* sDen = (float*)(sm + OFF_DEN);
    float dsum = den + __shfl_xor_sync(0xffffffffu, den, 1);
    dsum += __shfl_xor_sync(0xffffffffu, dsum, 2);
    if ((t & 3) == 0) sDen[prow] = dsum;
    __syncthreads();

    // ---- epilogue: normalize + ELU, float2 stores ----
    #pragma unroll
    for (int mi = 0; mi < 2; mi++) {
        const int rloc = m0 + 16 * mi + g;
        const int r0 = n0 + rloc;
        const float i0 = 1.0f / sDen[rloc];
        const float i1 = 1.0f / sDen[rloc + 8];
        #pragma unroll
        for (int ni = 0; ni < 4; ni++) {
            const int col = nb0 + 8 * ni + 2 * tig;
            float o0 = acc[mi][ni][0] * i0, o1 = acc[mi][ni][1] * i0;
            float o2 = acc[mi][ni][2] * i1, o3 = acc[mi][ni][3] * i1;
            o0 = (o0 > 0.f) ? o0 : expm1f(o0);
            o1 = (o1 > 0.f) ? o1 : expm1f(o1);
            o2 = (o2 > 0.f) ? o2 : expm1f(o2);
            o3 = (o3 > 0.f) ? o3 : expm1f(o3);
            float2 v0 = make_float2(o0, o1);
            float2 v1 = make_float2(o2, o3);
            *(float2*)&out[((size_t)(b * NN) + r0)     * FF + col] = v0;
            *(float2*)&out[((size_t)(b * NN) + r0 + 8) * FF + col] = v1;
        }
    }
}

// ============================================================================
extern "C" void kernel_launch(void* const* d_in, const int* in_sizes, int n_in,
                              void* d_out, int out_size) {
    const float* h   = (const float*)d_in[0];
    const int*   adj = (const int*)  d_in[1];
    const float* W   = (const float*)d_in[2];
    const float* av  = (const float*)d_in[3];
    float*       out = (float*)d_out;

    k_wh<<<(BB * NN) / 16, 128>>>(h, W, av);

    cudaFuncSetAttribute(k_attn, cudaFuncAttributeMaxDynamicSharedMemorySize, SMEM_DYN);
    k_attn<<<BB * (NN / QT), 256, SMEM_DYN>>>(adj, out);
}

// round 7
// speedup vs baseline: 2.8979x; 1.0685x over previous
#include <cuda_runtime.h>
#include <math.h>
#include <stdint.h>

#define BB   4
#define NN   4096
#define FIN  256
#define FF   128
#define QT   64                // query rows per block (k_attn)
#define KT   64                // key tile
#define ITERS (NN / KT)
#define PSTR 68                // padded stride (words) of P tile  -> conflict-free frags
#define BSTR 136               // padded stride (words) of Wh tile -> conflict-free frags
#define LRA  0.2f

typedef unsigned long long ull;

// Scratch (device globals: allocation-free rule)
__device__ float g_Wh [BB * NN * FF];   // 8 MB, tf32-rounded Wh (B operand)
__device__ float g_Wh1[BB * NN];
__device__ float g_Wh2[BB * NN];

// ---------------------------------------------------------------------------
__device__ __forceinline__ uint32_t cvt_tf32(float x) {
    uint32_t u;
    asm("cvt.rna.tf32.f32 %0, %1;" : "=r"(u) : "f"(x));
    return u;
}
__device__ __forceinline__ void mma_tf32(float* c, const uint32_t* a, const uint32_t* b) {
    asm volatile(
        "mma.sync.aligned.m16n8k8.row.col.f32.tf32.tf32.f32 "
        "{%0,%1,%2,%3}, {%4,%5,%6,%7}, {%8,%9}, {%0,%1,%2,%3};"
        : "+f"(c[0]), "+f"(c[1]), "+f"(c[2]), "+f"(c[3])
        : "r"(a[0]), "r"(a[1]), "r"(a[2]), "r"(a[3]), "r"(b[0]), "r"(b[1]));
}
__device__ __forceinline__ uint32_t smem_u32(const void* p) {
    uint32_t a;
    asm("{ .reg .u64 t; cvta.to.shared.u64 t, %1; cvt.u32.u64 %0, t; }"
        : "=r"(a) : "l"(p));
    return a;
}
__device__ __forceinline__ void cp16(uint32_t dst, const void* src) {
    asm volatile("cp.async.cg.shared.global [%0], [%1], 16;" :: "r"(dst), "l"(src));
}
// packed fp32x2 helpers (B300 2x fp32 path)
__device__ __forceinline__ ull ffma2(ull a, ull b, ull c) {
    ull d;
    asm("fma.rn.f32x2 %0, %1, %2, %3;" : "=l"(d) : "l"(a), "l"(b), "l"(c));
    return d;
}
__device__ __forceinline__ ull pack2s(float x) {
    ull p;
    asm("mov.b64 %0, {%1, %2};" : "=l"(p) : "f"(x), "f"(x));
    return p;
}
__device__ __forceinline__ ull packp(float lo, float hi) {
    ull p;
    asm("mov.b64 %0, {%1, %2};" : "=l"(p) : "f"(lo), "f"(hi));
    return p;
}
__device__ __forceinline__ float2 unp2(ull p) {
    float lo, hi;
    asm("mov.b64 {%0, %1}, %2;" : "=f"(lo), "=f"(hi) : "l"(p));
    return make_float2(lo, hi);
}

// ============================================================================
// Kernel 1: Wh = h @ W (tf32-rounded at store), fused Wh1/Wh2 (full fp32).
// Inner loop on packed fma.rn.f32x2 (2x fp32 rate, bit-identical rounding).
// ============================================================================
__global__ void k_wh(const float* __restrict__ h,
                     const float* __restrict__ W,
                     const float* __restrict__ av) {
    __shared__ float sh[16 * FIN];
    __shared__ float sa[2 * FF];

    const int t    = threadIdx.x;
    const int row0 = blockIdx.x * 16;

    const float4* src = (const float4*)(h + (size_t)row0 * FIN);
    #pragma unroll
    for (int i = 0; i < 8; i++) ((float4*)sh)[t + i * 128] = src[t + i * 128];
    if (t < 64) ((float4*)sa)[t] = ((const float4*)av)[t];
    __syncthreads();

    const int rg = t >> 5, cg = t & 31;
    const int c0 = cg * 4;

    ull accP[4][2];
    #pragma unroll
    for (int i = 0; i < 4; i++) { accP[i][0] = packp(0.f, 0.f); accP[i][1] = accP[i][0]; }

    #pragma unroll 4
    for (int k = 0; k < FIN; k++) {
        const float4 w4 = *(const float4*)(W + (size_t)k * FF + c0);
        const ull w01 = packp(w4.x, w4.y);
        const ull w23 = packp(w4.z, w4.w);
        #pragma unroll
        for (int i = 0; i < 4; i++) {
            const ull aa = pack2s(sh[(rg * 4 + i) * FIN + k]);
            accP[i][0] = ffma2(aa, w01, accP[i][0]);
            accP[i][1] = ffma2(aa, w23, accP[i][1]);
        }
    }

    #pragma unroll
    for (int i = 0; i < 4; i++) {
        const int row = row0 + rg * 4 + i;
        const float2 v01 = unp2(accP[i][0]);
        const float2 v23 = unp2(accP[i][1]);

        // store Wh pre-rounded to tf32 (B operand of the mma)
        uint4 uv;
        uv.x = cvt_tf32(v01.x);
        uv.y = cvt_tf32(v01.y);
        uv.z = cvt_tf32(v23.x);
        uv.w = cvt_tf32(v23.y);
        *(uint4*)&g_Wh[(size_t)row * FF + c0] = uv;

        // Wh1/Wh2 from full-precision acc
        float p1 = v01.x * sa[c0]          + v01.y * sa[c0 + 1]
                 + v23.x * sa[c0 + 2]      + v23.y * sa[c0 + 3];
        float p2 = v01.x * sa[FF + c0]     + v01.y * sa[FF + c0 + 1]
                 + v23.x * sa[FF + c0 + 2] + v23.y * sa[FF + c0 + 3];
        #pragma unroll
        for (int off = 16; off; off >>= 1) {
            p1 += __shfl_xor_sync(0xffffffffu, p1, off);
            p2 += __shfl_xor_sync(0xffffffffu, p2, off);
        }
        if (cg == 0) { g_Wh1[row] = p1; g_Wh2[row] = p2; }
    }
}

// ============================================================================
// Kernel 2: fused masked-softmax attention on tensor pipe (mma.sync tf32).
// Single-sync pipeline: P AND Wh tiles double-buffered; per tile, one
// __syncthreads; exp for tile it+1 and MMA for tile it share the inter-sync
// region (MUFU/ALU overlaps tensor). cp.async 2-deep. 2 CTAs/SM.
// ============================================================================
#define OFF_SP0 0
#define OFF_SP1 (QT * PSTR * 4)                  // 17408
#define OFF_SB0 (2 * QT * PSTR * 4)              // 34816
#define OFF_SB1 (OFF_SB0 + KT * BSTR * 4)        // 69632
#define OFF_DEN (OFF_SB1 + KT * BSTR * 4)        // 104448
#define SMEM_DYN (OFF_DEN + QT * 4)              // 104704

__global__ void __launch_bounds__(256, 2)
k_attn(const int* __restrict__ adj, float* __restrict__ out) {
    extern __shared__ char sm[];
    const uint32_t sbase = smem_u32(sm);

    const int t = threadIdx.x, lane = t & 31, wid = t >> 5;
    const int b = blockIdx.x >> 6;
    const int n0 = (blockIdx.x & 63) * QT;

    // phase-B geometry: 4 threads per row, 16 cols each
    const int prow = t >> 2;
    const int pcol = (t & 3) * 16;
    const float w1 = __ldg(&g_Wh1[b * NN + n0 + prow]);
    const int*   adjP = adj + ((size_t)(b * NN + n0 + prow)) * NN + pcol;
    const float* wh2P = g_Wh2 + b * NN + pcol;
    const float* whS  = g_Wh + (size_t)b * NN * FF;

    // cp.async Wh-tile stage (KT x FF), 8 float4 per thread
    auto cp_tile = [&](int mt, uint32_t bufOff) {
        #pragma unroll
        for (int i = 0; i < 8; i++) {
            const int q = t + i * 256;
            const int r = q >> 5, c4 = q & 31;
            cp16(sbase + bufOff + (uint32_t)(r * BSTR + c4 * 4) * 4,
                 whS + (size_t)(mt + r) * FF + c4 * 4);
        }
        asm volatile("cp.async.commit_group;" ::: "memory");
    };

    float den = 0.f;
    uint4 pv[4];

    // masked-exp P values for tile at key offset mt (adjR already loaded)
    auto compute_pv = [&](int mt, const int4* adjR) {
        #pragma unroll
        for (int j = 0; j < 4; j++) {
            const float4 w2 = __ldg((const float4*)(wh2P + mt) + j);
            float s0 = w1 + w2.x; s0 = fmaxf(s0, LRA * s0);
            float s1 = w1 + w2.y; s1 = fmaxf(s1, LRA * s1);
            float s2 = w1 + w2.z; s2 = fmaxf(s2, LRA * s2);
            float s3 = w1 + w2.w; s3 = fmaxf(s3, LRA * s3);
            pv[j].x = cvt_tf32((adjR[j].x > 0) ? __expf(s0) : 0.f);
            pv[j].y = cvt_tf32((adjR[j].y > 0) ? __expf(s1) : 0.f);
            pv[j].z = cvt_tf32((adjR[j].z > 0) ? __expf(s2) : 0.f);
            pv[j].w = cvt_tf32((adjR[j].w > 0) ? __expf(s3) : 0.f);
            den += (__uint_as_float(pv[j].x) + __uint_as_float(pv[j].y))
                 + (__uint_as_float(pv[j].z) + __uint_as_float(pv[j].w));
        }
    };
    auto store_pv = [&](uint32_t pOff) {
        uint32_t* d = (uint32_t*)(sm + pOff) + prow * PSTR + pcol;
        #pragma unroll
        for (int j = 0; j < 4; j++) *(uint4*)(d + 4 * j) = pv[j];
    };

    // ---- prologue: tile 0 ----
    {
        int4 adjR[4];
        #pragma unroll
        for (int j = 0; j < 4; j++) adjR[j] = __ldg((const int4*)adjP + j);
        cp_tile(0, OFF_SB0);
        compute_pv(0, adjR);
        store_pv(OFF_SP0);
    }

    float acc[2][4][4];
    #pragma unroll
    for (int mi = 0; mi < 2; mi++)
        #pragma unroll
        for (int ni = 0; ni < 4; ni++)
            #pragma unroll
            for (int q = 0; q < 4; q++) acc[mi][ni][q] = 0.f;

    const int g = lane >> 2, tig = lane & 3;
    const int m0 = (wid & 1) * 32, nb0 = (wid >> 1) * 32;

    for (int it = 0; it < ITERS; ++it) {
        const int buf = it & 1;
        const uint32_t pOff = buf ? OFF_SP1 : OFF_SP0;
        const uint32_t bOff = buf ? OFF_SB1 : OFF_SB0;

        // one barrier per tile: P[buf] visible; prior MMAs on [buf^1] done
        __syncthreads();

        // prefetch Wh tile it+1 into B[buf^1] (read last at iter it-1)
        if (it + 1 < ITERS) cp_tile((it + 1) * KT, buf ? OFF_SB0 : OFF_SB1);
        else asm volatile("cp.async.commit_group;" ::: "memory");
        // ensure Wh tile it (group issued at iter it-1) has landed
        asm volatile("cp.async.wait_group 1;" ::: "memory");

        // exp for tile it+1 (overlaps the MMA block below across pipes)
        if (it + 1 < ITERS) {
            int4 adjR[4];
            const int mtn = (it + 1) * KT;
            #pragma unroll
            for (int j = 0; j < 4; j++)
                adjR[j] = __ldg((const int4*)(adjP + mtn) + j);
            compute_pv(mtn, adjR);
            store_pv(buf ? OFF_SP0 : OFF_SP1);
        }

        // ---- MMA: acc += P[QTxKT] @ Wh[KTx128] ----
        const uint32_t* A = (const uint32_t*)(sm + pOff);
        const uint32_t* B = (const uint32_t*)(sm + bOff);
        #pragma unroll 2
        for (int ks = 0; ks < 8; ++ks) {
            const int k0 = ks * 8;
            uint32_t af[2][4];
            #pragma unroll
            for (int mi = 0; mi < 2; mi++) {
                const uint32_t* ap = A + (m0 + 16 * mi + g) * PSTR + k0 + tig;
                af[mi][0] = ap[0];
                af[mi][1] = ap[8 * PSTR];
                af[mi][2] = ap[4];
                af[mi][3] = ap[8 * PSTR + 4];
            }
            uint32_t bf[4][2];
            #pragma unroll
            for (int ni = 0; ni < 4; ni++) {
                const uint32_t* bp = B + (k0 + tig) * BSTR + nb0 + 8 * ni + g;
                bf[ni][0] = bp[0];
                bf[ni][1] = bp[4 * BSTR];
            }
            #pragma unroll
            for (int mi = 0; mi < 2; mi++)
                #pragma unroll
                for (int ni = 0; ni < 4; ni++)
                    mma_tf32(acc[mi][ni], af[mi], bf[ni]);
        }
    }

    // ---- denominator: reduce across the 4 threads sharing a row ----
    float* sDen = (float*)(sm + OFF_DEN);
    float dsum = den + __shfl_xor_sync(0xffffffffu, den, 1);
    dsum += __shfl_xor_sync(0xffffffffu, dsum, 2);
    __syncthreads();
    if ((t & 3) == 0) sDen[prow] = dsum;
    __syncthreads();

    // ---- epilogue: normalize + ELU, float2 stores ----
    #pragma unroll
    for (int mi = 0; mi < 2; mi++) {
        const int rloc = m0 + 16 * mi + g;
        const int r0 = n0 + rloc;
        const float i0 = 1.0f / sDen[rloc];
        const float i1 = 1.0f / sDen[rloc + 8];
        #pragma unroll
        for (int ni = 0; ni < 4; ni++) {
            const int col = nb0 + 8 * ni + 2 * tig;
            float o0 = acc[mi][ni][0] * i0, o1 = acc[mi][ni][1] * i0;
            float o2 = acc[mi][ni][2] * i1, o3 = acc[mi][ni][3] * i1;
            o0 = (o0 > 0.f) ? o0 : expm1f(o0);
            o1 = (o1 > 0.f) ? o1 : expm1f(o1);
            o2 = (o2 > 0.f) ? o2 : expm1f(o2);
            o3 = (o3 > 0.f) ? o3 : expm1f(o3);
            float2 v0 = make_float2(o0, o1);
            float2 v1 = make_float2(o2, o3);
            *(float2*)&out[((size_t)(b * NN) + r0)     * FF + col] = v0;
            *(float2*)&out[((size_t)(b * NN) + r0 + 8) * FF + col] = v1;
        }
    }
}

// ============================================================================
extern "C" void kernel_launch(void* const* d_in, const int* in_sizes, int n_in,
                              void* d_out, int out_size) {
    const float* h   = (const float*)d_in[0];
    const int*   adj = (const int*)  d_in[1];
    const float* W   = (const float*)d_in[2];
    const float* av  = (const float*)d_in[3];
    float*       out = (float*)d_out;

    k_wh<<<(BB * NN) / 16, 128>>>(h, W, av);

    cudaFuncSetAttribute(k_attn, cudaFuncAttributeMaxDynamicSharedMemorySize, SMEM_DYN);
    k_attn<<<BB * (NN / QT), 256, SMEM_DYN>>>(adj, out);
}

// round 8
// speedup vs baseline: 3.0469x; 1.0514x over previous
#include <cuda_runtime.h>
#include <math.h>
#include <stdint.h>

#define BB   4
#define NN   4096
#define FIN  256
#define FF   128
#define QT   64                // query rows per block (k_attn)
#define KT   64                // key tile
#define ITERS (NN / KT)
#define ASTR 72                // words per P-tile row (8 k8-blocks * 8 + 8 pad)
#define LRA  0.2f

typedef unsigned long long ull;

// Scratch (device globals: allocation-free rule)
// g_Wh holds tf32-rounded Wh in PAIR layout: word index =
//   (row>>3)*1024 + f*8 + (row&3)*2 + ((row>>2)&1)
// so the mma B-fragment (B[k][n], B[k+4][n]) is one aligned 8-byte pair.
__device__ float g_Wh [BB * NN * FF];   // 8 MB
__device__ float g_Wh1[BB * NN];
__device__ float g_Wh2[BB * NN];

// ---------------------------------------------------------------------------
__device__ __forceinline__ uint32_t cvt_tf32(float x) {
    uint32_t u;
    asm("cvt.rna.tf32.f32 %0, %1;" : "=r"(u) : "f"(x));
    return u;
}
__device__ __forceinline__ void mma_tf32(float* c, const uint32_t* a, const uint32_t* b) {
    asm volatile(
        "mma.sync.aligned.m16n8k8.row.col.f32.tf32.tf32.f32 "
        "{%0,%1,%2,%3}, {%4,%5,%6,%7}, {%8,%9}, {%0,%1,%2,%3};"
        : "+f"(c[0]), "+f"(c[1]), "+f"(c[2]), "+f"(c[3])
        : "r"(a[0]), "r"(a[1]), "r"(a[2]), "r"(a[3]), "r"(b[0]), "r"(b[1]));
}
__device__ __forceinline__ uint32_t smem_u32(const void* p) {
    uint32_t a;
    asm("{ .reg .u64 t; cvta.to.shared.u64 t, %1; cvt.u32.u64 %0, t; }"
        : "=r"(a) : "l"(p));
    return a;
}
__device__ __forceinline__ void cp16(uint32_t dst, const void* src) {
    asm volatile("cp.async.cg.shared.global [%0], [%1], 16;" :: "r"(dst), "l"(src));
}
// packed fp32x2 helpers (B300 2x fp32 path)
__device__ __forceinline__ ull ffma2(ull a, ull b, ull c) {
    ull d;
    asm("fma.rn.f32x2 %0, %1, %2, %3;" : "=l"(d) : "l"(a), "l"(b), "l"(c));
    return d;
}
__device__ __forceinline__ ull pack2s(float x) {
    ull p;
    asm("mov.b64 %0, {%1, %2};" : "=l"(p) : "f"(x), "f"(x));
    return p;
}
__device__ __forceinline__ ull packp(float lo, float hi) {
    ull p;
    asm("mov.b64 %0, {%1, %2};" : "=l"(p) : "f"(lo), "f"(hi));
    return p;
}
__device__ __forceinline__ float2 unp2(ull p) {
    float lo, hi;
    asm("mov.b64 {%0, %1}, %2;" : "=f"(lo), "=f"(hi) : "l"(p));
    return make_float2(lo, hi);
}

// ============================================================================
// Kernel 1: Wh = h @ W on packed fma.rn.f32x2; Wh stored tf32-rounded in the
// MMA pair layout; fused Wh1/Wh2 (full fp32) via warp reduction.
// ============================================================================
__global__ void k_wh(const float* __restrict__ h,
                     const float* __restrict__ W,
                     const float* __restrict__ av) {
    __shared__ float sh[16 * FIN];
    __shared__ float sa[2 * FF];

    const int t    = threadIdx.x;
    const int row0 = blockIdx.x * 16;

    const float4* src = (const float4*)(h + (size_t)row0 * FIN);
    #pragma unroll
    for (int i = 0; i < 8; i++) ((float4*)sh)[t + i * 128] = src[t + i * 128];
    if (t < 64) ((float4*)sa)[t] = ((const float4*)av)[t];
    __syncthreads();

    const int rg = t >> 5, cg = t & 31;
    const int c0 = cg * 4;

    ull accP[4][2];
    #pragma unroll
    for (int i = 0; i < 4; i++) { accP[i][0] = packp(0.f, 0.f); accP[i][1] = accP[i][0]; }

    #pragma unroll 4
    for (int k = 0; k < FIN; k++) {
        const float4 w4 = *(const float4*)(W + (size_t)k * FF + c0);
        const ull w01 = packp(w4.x, w4.y);
        const ull w23 = packp(w4.z, w4.w);
        #pragma unroll
        for (int i = 0; i < 4; i++) {
            const ull aa = pack2s(sh[(rg * 4 + i) * FIN + k]);
            accP[i][0] = ffma2(aa, w01, accP[i][0]);
            accP[i][1] = ffma2(aa, w23, accP[i][1]);
        }
    }

    uint32_t* gW = (uint32_t*)g_Wh;
    #pragma unroll
    for (int i = 0; i < 4; i++) {
        const int row = row0 + rg * 4 + i;
        const float2 v01 = unp2(accP[i][0]);
        const float2 v23 = unp2(accP[i][1]);

        // pair-layout tf32 store
        const int kb = row >> 3, tg = row & 3, hi = (row >> 2) & 1;
        uint32_t* base = gW + (size_t)kb * 1024 + tg * 2 + hi;
        base[(size_t)(c0 + 0) * 8] = cvt_tf32(v01.x);
        base[(size_t)(c0 + 1) * 8] = cvt_tf32(v01.y);
        base[(size_t)(c0 + 2) * 8] = cvt_tf32(v23.x);
        base[(size_t)(c0 + 3) * 8] = cvt_tf32(v23.y);

        // Wh1/Wh2 from full-precision acc
        float p1 = v01.x * sa[c0]          + v01.y * sa[c0 + 1]
                 + v23.x * sa[c0 + 2]      + v23.y * sa[c0 + 3];
        float p2 = v01.x * sa[FF + c0]     + v01.y * sa[FF + c0 + 1]
                 + v23.x * sa[FF + c0 + 2] + v23.y * sa[FF + c0 + 3];
        #pragma unroll
        for (int off = 16; off; off >>= 1) {
            p1 += __shfl_xor_sync(0xffffffffu, p1, off);
            p2 += __shfl_xor_sync(0xffffffffu, p2, off);
        }
        if (cg == 0) { g_Wh1[row] = p1; g_Wh2[row] = p2; }
    }
}

// ============================================================================
// Kernel 2: fused masked-softmax attention on tensor pipe (mma.sync tf32).
// 512 threads/CTA, 2 CTAs/SM -> 32 warps/SM. 16 warps = 2(m) x 4(n) x 2(k-split)
// over the 64x128 output tile; k-halves merged once at the end. P and Wh tiles
// double-buffered, pair-interleaved fragments (all frag reads are LDS.64),
// single __syncthreads per tile; exp(it+1) overlaps MMA(it) across pipes.
// ============================================================================
#define OFF_SA0 0
#define OFF_SA1 18432
#define OFF_SB0 36864
#define OFF_SB1 69632
#define OFF_DEN 102400
#define SMEM_DYN 102656

__global__ void __launch_bounds__(512, 2)
k_attn(const int* __restrict__ adj, float* __restrict__ out) {
    extern __shared__ char sm[];
    const uint32_t sbase = smem_u32(sm);

    const int t = threadIdx.x, lane = t & 31, wid = t >> 5;
    const int b = blockIdx.x >> 6;
    const int n0 = (blockIdx.x & 63) * QT;

    // phase-B geometry: 8 threads per row, 8 cols (one k8 block) each
    const int prow = t >> 3;
    const int pk8  = t & 7;
    const float w1 = __ldg(&g_Wh1[b * NN + n0 + prow]);
    const int*      adjP   = adj + ((size_t)(b * NN + n0 + prow)) * NN + pk8 * 8;
    const float*    wh2P   = g_Wh2 + b * NN + pk8 * 8;
    const uint32_t* whPair = (const uint32_t*)g_Wh;

    // cp.async Wh-tile stage: straight 32KB copy (pair layout is contiguous)
    auto cp_tile = [&](int mt, uint32_t bufOff) {
        const float4* src = (const float4*)whPair + ((size_t)(b * NN + mt)) * 32;
        #pragma unroll
        for (int i = 0; i < 4; i++) {
            const int q = t + i * 512;
            cp16(sbase + bufOff + (uint32_t)q * 16, src + q);
        }
        asm volatile("cp.async.commit_group;" ::: "memory");
    };

    float den = 0.f;
    uint4 u0, u1;     // pair-interleaved P fragment words

    auto compute_pv = [&](int mt) {
        const int4 a0 = __ldg((const int4*)(adjP + mt));
        const int4 a1 = __ldg((const int4*)(adjP + mt) + 1);
        const float4 w2a = __ldg((const float4*)(wh2P + mt));
        const float4 w2b = __ldg((const float4*)(wh2P + mt) + 1);
        float s0 = w1 + w2a.x; s0 = fmaxf(s0, LRA * s0);
        float s1 = w1 + w2a.y; s1 = fmaxf(s1, LRA * s1);
        float s2 = w1 + w2a.z; s2 = fmaxf(s2, LRA * s2);
        float s3 = w1 + w2a.w; s3 = fmaxf(s3, LRA * s3);
        float s4 = w1 + w2b.x; s4 = fmaxf(s4, LRA * s4);
        float s5 = w1 + w2b.y; s5 = fmaxf(s5, LRA * s5);
        float s6 = w1 + w2b.z; s6 = fmaxf(s6, LRA * s6);
        float s7 = w1 + w2b.w; s7 = fmaxf(s7, LRA * s7);
        const uint32_t p0 = cvt_tf32((a0.x > 0) ? __expf(s0) : 0.f);
        const uint32_t p1 = cvt_tf32((a0.y > 0) ? __expf(s1) : 0.f);
        const uint32_t p2 = cvt_tf32((a0.z > 0) ? __expf(s2) : 0.f);
        const uint32_t p3 = cvt_tf32((a0.w > 0) ? __expf(s3) : 0.f);
        const uint32_t p4 = cvt_tf32((a1.x > 0) ? __expf(s4) : 0.f);
        const uint32_t p5 = cvt_tf32((a1.y > 0) ? __expf(s5) : 0.f);
        const uint32_t p6 = cvt_tf32((a1.z > 0) ? __expf(s6) : 0.f);
        const uint32_t p7 = cvt_tf32((a1.w > 0) ? __expf(s7) : 0.f);
        den += (__uint_as_float(p0) + __uint_as_float(p1))
             + (__uint_as_float(p2) + __uint_as_float(p3))
             + (__uint_as_float(p4) + __uint_as_float(p5))
             + (__uint_as_float(p6) + __uint_as_float(p7));
        u0.x = p0; u0.y = p4; u0.z = p1; u0.w = p5;   // pairs (c, c+4)
        u1.x = p2; u1.y = p6; u1.z = p3; u1.w = p7;
    };
    auto store_pv = [&](uint32_t pOff) {
        uint32_t* d = (uint32_t*)(sm + pOff) + prow * ASTR + pk8 * 8;
        *(uint4*)d       = u0;
        *(uint4*)(d + 4) = u1;
    };

    // ---- prologue: tile 0 ----
    cp_tile(0, OFF_SB0);
    compute_pv(0);
    store_pv(OFF_SA0);

    float acc[2][4][4];
    #pragma unroll
    for (int mi = 0; mi < 2; mi++)
        #pragma unroll
        for (int ni = 0; ni < 4; ni++)
            #pragma unroll
            for (int q = 0; q < 4; q++) acc[mi][ni][q] = 0.f;

    const int g = lane >> 2, tig = lane & 3;
    const int m0  = (wid & 1) * 32;
    const int nb0 = ((wid >> 1) & 3) * 32;
    const int kh  = wid >> 3;                 // k-split half

    for (int it = 0; it < ITERS; ++it) {
        const int buf = it & 1;
        const uint32_t pOff = buf ? OFF_SA1 : OFF_SA0;
        const uint32_t bOff = buf ? OFF_SB1 : OFF_SB0;

        // one barrier per tile: P[buf] visible; prior MMAs on [buf^1] done
        __syncthreads();

        // prefetch Wh tile it+1 into B[buf^1]
        if (it + 1 < ITERS) cp_tile((it + 1) * KT, buf ? OFF_SB0 : OFF_SB1);
        else asm volatile("cp.async.commit_group;" ::: "memory");
        asm volatile("cp.async.wait_group 1;" ::: "memory");

        // exp for tile it+1 (overlaps MMA below across pipes)
        if (it + 1 < ITERS) {
            compute_pv((it + 1) * KT);
            store_pv(buf ? OFF_SA0 : OFF_SA1);
        }

        // ---- MMA: acc += P[QT x KT-half] @ Wh[KT-half x 128] ----
        const uint32_t* A = (const uint32_t*)(sm + pOff);
        const uint32_t* B = (const uint32_t*)(sm + bOff);
        #pragma unroll
        for (int ks = 0; ks < 4; ++ks) {
            const int k8 = kh * 4 + ks;
            uint32_t af[2][4];
            #pragma unroll
            for (int mi = 0; mi < 2; mi++) {
                const uint32_t* ap = A + (m0 + 16 * mi + g) * ASTR + k8 * 8 + tig * 2;
                const uint2 pA = *(const uint2*)ap;              // (a0, a2)
                const uint2 pB = *(const uint2*)(ap + 8 * ASTR); // (a1, a3)
                af[mi][0] = pA.x; af[mi][1] = pB.x;
                af[mi][2] = pA.y; af[mi][3] = pB.y;
            }
            uint32_t bf[4][2];
            #pragma unroll
            for (int ni = 0; ni < 4; ni++) {
                const uint2 pb = *(const uint2*)(B + k8 * 1024
                                    + (nb0 + 8 * ni + g) * 8 + tig * 2);
                bf[ni][0] = pb.x; bf[ni][1] = pb.y;
            }
            #pragma unroll
            for (int mi = 0; mi < 2; mi++)
                #pragma unroll
                for (int ni = 0; ni < 4; ni++)
                    mma_tf32(acc[mi][ni], af[mi], bf[ni]);
        }
    }

    __syncthreads();   // all MMAs done; SMEM reusable

    // ---- denominator: reduce across the 8 threads sharing a row ----
    float* sDen = (float*)(sm + OFF_DEN);
    float dsum = den + __shfl_xor_sync(0xffffffffu, den, 1);
    dsum += __shfl_xor_sync(0xffffffffu, dsum, 2);
    dsum += __shfl_xor_sync(0xffffffffu, dsum, 4);
    if ((t & 7) == 0) sDen[prow] = dsum;

    // ---- k-split merge: kh=1 warps park accs in SMEM (padded stride 36) ----
    float* red = (float*)(sm + OFF_SB0);
    if (kh == 1) {
        float* slot = red + ((size_t)((wid - 8) * 32 + lane)) * 36;
        #pragma unroll
        for (int mi = 0; mi < 2; mi++)
            #pragma unroll
            for (int ni = 0; ni < 4; ni++)
                *(float4*)(slot + (mi * 4 + ni) * 4) = *(float4*)acc[mi][ni];
    }
    __syncthreads();

    if (kh == 0) {
        const float* slot = red + ((size_t)(wid * 32 + lane)) * 36;
        #pragma unroll
        for (int mi = 0; mi < 2; mi++)
            #pragma unroll
            for (int ni = 0; ni < 4; ni++) {
                const float4 v = *(const float4*)(slot + (mi * 4 + ni) * 4);
                acc[mi][ni][0] += v.x; acc[mi][ni][1] += v.y;
                acc[mi][ni][2] += v.z; acc[mi][ni][3] += v.w;
            }

        // ---- epilogue: normalize + ELU, float2 stores ----
        #pragma unroll
        for (int mi = 0; mi < 2; mi++) {
            const int rloc = m0 + 16 * mi + g;
            const int r0 = n0 + rloc;
            const float i0 = 1.0f / sDen[rloc];
            const float i1 = 1.0f / sDen[rloc + 8];
            #pragma unroll
            for (int ni = 0; ni < 4; ni++) {
                const int col = nb0 + 8 * ni + 2 * tig;
                float o0 = acc[mi][ni][0] * i0, o1 = acc[mi][ni][1] * i0;
                float o2 = acc[mi][ni][2] * i1, o3 = acc[mi][ni][3] * i1;
                o0 = (o0 > 0.f) ? o0 : expm1f(o0);
                o1 = (o1 > 0.f) ? o1 : expm1f(o1);
                o2 = (o2 > 0.f) ? o2 : expm1f(o2);
                o3 = (o3 > 0.f) ? o3 : expm1f(o3);
                *(float2*)&out[((size_t)(b * NN) + r0)     * FF + col] = make_float2(o0, o1);
                *(float2*)&out[((size_t)(b * NN) + r0 + 8) * FF + col] = make_float2(o2, o3);
            }
        }
    }
}

// ============================================================================
extern "C" void kernel_launch(void* const* d_in, const int* in_sizes, int n_in,
                              void* d_out, int out_size) {
    const float* h   = (const float*)d_in[0];
    const int*   adj = (const int*)  d_in[1];
    const float* W   = (const float*)d_in[2];
    const float* av  = (const float*)d_in[3];
    float*       out = (float*)d_out;

    k_wh<<<(BB * NN) / 16, 128>>>(h, W, av);

    cudaFuncSetAttribute(k_attn, cudaFuncAttributeMaxDynamicSharedMemorySize, SMEM_DYN);
    k_attn<<<BB * (NN / QT), 512, SMEM_DYN>>>(adj, out);
}

// round 11
// speedup vs baseline: 3.1543x; 1.0352x over previous
#include <cuda_runtime.h>
#include <math.h>
#include <stdint.h>

#define BB   4
#define NN   4096
#define FIN  256
#define FF   128
#define QT   64                // query rows per block (k_attn)
#define KT   64                // key tile
#define ITERS (NN / KT)
#define ASTR 72                // words per P-tile row (8 k8-blocks * 8 + 8 pad)
#define LRA  0.2f

typedef unsigned long long ull;

// Scratch (device globals: allocation-free rule)
// g_Wh holds tf32-rounded Wh in PAIR layout: word index =
//   (row>>3)*1024 + f*8 + (row&3)*2 + ((row>>2)&1)
// so the mma B-fragment (B[k][n], B[k+4][n]) is one aligned 8-byte pair.
__device__ float g_Wh [BB * NN * FF];   // 8 MB
__device__ float g_Wh1[BB * NN];
__device__ float g_Wh2[BB * NN];

// ---------------------------------------------------------------------------
__device__ __forceinline__ uint32_t cvt_tf32(float x) {
    uint32_t u;
    asm("cvt.rna.tf32.f32 %0, %1;" : "=r"(u) : "f"(x));
    return u;
}
__device__ __forceinline__ void mma_tf32(float* c, const uint32_t* a, const uint32_t* b) {
    asm volatile(
        "mma.sync.aligned.m16n8k8.row.col.f32.tf32.tf32.f32 "
        "{%0,%1,%2,%3}, {%4,%5,%6,%7}, {%8,%9}, {%0,%1,%2,%3};"
        : "+f"(c[0]), "+f"(c[1]), "+f"(c[2]), "+f"(c[3])
        : "r"(a[0]), "r"(a[1]), "r"(a[2]), "r"(a[3]), "r"(b[0]), "r"(b[1]));
}
__device__ __forceinline__ uint32_t smem_u32(const void* p) {
    uint32_t a;
    asm("{ .reg .u64 t; cvta.to.shared.u64 t, %1; cvt.u32.u64 %0, t; }"
        : "=r"(a) : "l"(p));
    return a;
}
__device__ __forceinline__ void cp16(uint32_t dst, const void* src) {
    asm volatile("cp.async.cg.shared.global [%0], [%1], 16;" :: "r"(dst), "l"(src));
}
// packed fp32x2 helpers (B300 2x fp32 path)
__device__ __forceinline__ ull ffma2(ull a, ull b, ull c) {
    ull d;
    asm("fma.rn.f32x2 %0, %1, %2, %3;" : "=l"(d) : "l"(a), "l"(b), "l"(c));
    return d;
}
__device__ __forceinline__ ull pack2s(float x) {
    ull p;
    asm("mov.b64 %0, {%1, %2};" : "=l"(p) : "f"(x), "f"(x));
    return p;
}
__device__ __forceinline__ ull packp(float lo, float hi) {
    ull p;
    asm("mov.b64 %0, {%1, %2};" : "=l"(p) : "f"(lo), "f"(hi));
    return p;
}
__device__ __forceinline__ float2 unp2(ull p) {
    float lo, hi;
    asm("mov.b64 {%0, %1}, %2;" : "=f"(lo), "=f"(hi) : "l"(p));
    return make_float2(lo, hi);
}

// ============================================================================
// Kernel 1: Wh = h @ W on packed fma.rn.f32x2.
// 256 threads, 64 rows/block; thread tile 4 rows x 8 cols (16 col-threads/row
// -> each warp reads a W row ONCE, intra-warp dedup halves W L1 traffic);
// h loaded as float4 (k-unroll 4). Rows assigned as {r, r+4} pairs within an
// 8-row block so the tf32 pair-layout store is uint2 (16 STG.64/thread).
// Fused Wh1/Wh2 via 16-lane shuffle reduction.
// ============================================================================
#define SMEM_WH (64 * FIN * 4 + 2 * FF * 4)

__global__ void __launch_bounds__(256, 2)
k_wh(const float* __restrict__ h,
     const float* __restrict__ W,
     const float* __restrict__ av) {
    extern __shared__ char smw[];
    float* sh = (float*)smw;                  // 64 x 256 h tile
    float* sa = sh + 64 * FIN;

    const int t    = threadIdx.x;
    const int row0 = blockIdx.x * 64;

    const float4* src = (const float4*)(h + (size_t)row0 * FIN);
    #pragma unroll
    for (int i = 0; i < 16; i++) ((float4*)sh)[t + i * 256] = src[t + i * 256];
    if (t < 64) ((float4*)sa)[t] = ((const float4*)av)[t];
    __syncthreads();

    const int rg = t >> 4, cg = t & 15;
    const int c0 = cg * 8;
    const int kb = rg & 7, hp = rg >> 3;
    int rowIdx[4];
    #pragma unroll
    for (int i = 0; i < 4; i++)
        rowIdx[i] = kb * 8 + hp * 2 + (i >> 1) + (i & 1) * 4;

    ull acc[4][4];
    #pragma unroll
    for (int i = 0; i < 4; i++)
        #pragma unroll
        for (int j = 0; j < 4; j++) acc[i][j] = 0ull;

    const float4* sh4 = (const float4*)sh;
    #pragma unroll 2
    for (int k0 = 0; k0 < FIN; k0 += 4) {
        float4 hv[4];
        #pragma unroll
        for (int i = 0; i < 4; i++) hv[i] = sh4[rowIdx[i] * 64 + (k0 >> 2)];
        #pragma unroll
        for (int kk = 0; kk < 4; kk++) {
            const float* wr = W + (size_t)(k0 + kk) * FF + c0;
            const float4 wa = *(const float4*)wr;
            const float4 wb = *(const float4*)(wr + 4);
            const ull w0 = packp(wa.x, wa.y), w1 = packp(wa.z, wa.w);
            const ull w2 = packp(wb.x, wb.y), w3 = packp(wb.z, wb.w);
            #pragma unroll
            for (int i = 0; i < 4; i++) {
                const ull aa = pack2s(((const float*)&hv[i])[kk]);
                acc[i][0] = ffma2(aa, w0, acc[i][0]);
                acc[i][1] = ffma2(aa, w1, acc[i][1]);
                acc[i][2] = ffma2(aa, w2, acc[i][2]);
                acc[i][3] = ffma2(aa, w3, acc[i][3]);
            }
        }
    }

    // unpack accs
    float v[4][8];
    #pragma unroll
    for (int i = 0; i < 4; i++)
        #pragma unroll
        for (int j = 0; j < 4; j++) {
            const float2 p = unp2(acc[i][j]);
            v[i][2 * j] = p.x; v[i][2 * j + 1] = p.y;
        }

    // pair-layout tf32 stores: (hi=0, hi=1) rows combine into one uint2
    uint32_t* gW = (uint32_t*)g_Wh;
    const int kbG = (row0 >> 3) + kb;
    #pragma unroll
    for (int ip = 0; ip < 2; ip++) {
        const int i0 = ip * 2;
        const int tg = hp * 2 + ip;
        uint32_t* base = gW + (size_t)kbG * 1024 + tg * 2;
        #pragma unroll
        for (int j = 0; j < 8; j++) {
            uint2 u; u.x = cvt_tf32(v[i0][j]); u.y = cvt_tf32(v[i0 + 1][j]);
            *(uint2*)(base + (size_t)(c0 + j) * 8) = u;
        }
    }

    // Wh1/Wh2 (full fp32): reduce across the 16 col-threads (half-warp)
    #pragma unroll
    for (int i = 0; i < 4; i++) {
        const int row = row0 + rowIdx[i];
        float p1 = 0.f, p2 = 0.f;
        #pragma unroll
        for (int j = 0; j < 8; j++) {
            p1 += v[i][j] * sa[c0 + j];
            p2 += v[i][j] * sa[FF + c0 + j];
        }
        #pragma unroll
        for (int off = 8; off; off >>= 1) {
            p1 += __shfl_xor_sync(0xffffffffu, p1, off);
            p2 += __shfl_xor_sync(0xffffffffu, p2, off);
        }
        if (cg == 0) { g_Wh1[row] = p1; g_Wh2[row] = p2; }
    }
}

// ============================================================================
// Kernel 2: fused masked-softmax attention on tensor pipe (mma.sync tf32).
// 512 threads/CTA, 2 CTAs/SM. Region structure per key tile:
//   barrier -> cp.async(B tile + ADJ tile for it+1) -> MMA(it) -> wait ->
//   exp(it+1) reading adj from SMEM (DRAM latency hidden under MMA).
// RACE FIX vs R9: each thread cp.asyncs EXACTLY the 32 adj bytes it later
// reads (writer == reader), so per-thread cp.async.wait_group ordering is
// sufficient — no cross-thread visibility needed before the barrier.
// ============================================================================
#define OFF_SA0 0
#define OFF_SA1 18432
#define OFF_SB0 36864
#define OFF_SB1 69632
#define OFF_DEN 102400
#define SMEM_DYN 102656

__global__ void __launch_bounds__(512, 2)
k_attn(const int* __restrict__ adj, float* __restrict__ out) {
    extern __shared__ char sm[];
    const uint32_t sbase = smem_u32(sm);

    const int t = threadIdx.x, lane = t & 31, wid = t >> 5;
    const int b = blockIdx.x >> 6;
    const int n0 = (blockIdx.x & 63) * QT;

    // phase-B geometry: 8 threads per row, 8 cols (one k8 block) each
    const int prow = t >> 3;
    const int pk8  = t & 7;
    const float w1 = __ldg(&g_Wh1[b * NN + n0 + prow]);
    const float*    wh2P   = g_Wh2 + b * NN + pk8 * 8;
    const uint32_t* whPair = (const uint32_t*)g_Wh;
    const int* adjThr = adj + (size_t)(b * NN + n0 + prow) * NN + pk8 * 8;
    const uint32_t thrWords = (uint32_t)(prow * ASTR + pk8 * 8) * 4; // byte off

    // cp.async Wh-tile stage: straight 32KB copy (pair layout is contiguous)
    auto cp_tileB = [&](int mt, uint32_t bufOff) {
        const float4* src = (const float4*)whPair + ((size_t)(b * NN + mt)) * 32;
        #pragma unroll
        for (int i = 0; i < 4; i++) {
            const int q = t + i * 512;
            cp16(sbase + bufOff + (uint32_t)q * 16, src + q);
        }
    };
    // adj tile: each thread stages its OWN 32 bytes (writer == reader)
    auto cp_adj = [&](int mt, uint32_t pOff) {
        cp16(sbase + pOff + thrWords,      adjThr + mt);
        cp16(sbase + pOff + thrWords + 16, adjThr + mt + 4);
    };

    float den = 0.f;
    uint4 u0, u1;     // pair-interleaved P fragment words

    auto compute_pv = [&](int mt, int4 a0, int4 a1) {
        const float4 w2a = __ldg((const float4*)(wh2P + mt));
        const float4 w2b = __ldg((const float4*)(wh2P + mt) + 1);
        float s0 = w1 + w2a.x; s0 = fmaxf(s0, LRA * s0);
        float s1 = w1 + w2a.y; s1 = fmaxf(s1, LRA * s1);
        float s2 = w1 + w2a.z; s2 = fmaxf(s2, LRA * s2);
        float s3 = w1 + w2a.w; s3 = fmaxf(s3, LRA * s3);
        float s4 = w1 + w2b.x; s4 = fmaxf(s4, LRA * s4);
        float s5 = w1 + w2b.y; s5 = fmaxf(s5, LRA * s5);
        float s6 = w1 + w2b.z; s6 = fmaxf(s6, LRA * s6);
        float s7 = w1 + w2b.w; s7 = fmaxf(s7, LRA * s7);
        const uint32_t p0 = cvt_tf32((a0.x > 0) ? __expf(s0) : 0.f);
        const uint32_t p1 = cvt_tf32((a0.y > 0) ? __expf(s1) : 0.f);
        const uint32_t p2 = cvt_tf32((a0.z > 0) ? __expf(s2) : 0.f);
        const uint32_t p3 = cvt_tf32((a0.w > 0) ? __expf(s3) : 0.f);
        const uint32_t p4 = cvt_tf32((a1.x > 0) ? __expf(s4) : 0.f);
        const uint32_t p5 = cvt_tf32((a1.y > 0) ? __expf(s5) : 0.f);
        const uint32_t p6 = cvt_tf32((a1.z > 0) ? __expf(s6) : 0.f);
        const uint32_t p7 = cvt_tf32((a1.w > 0) ? __expf(s7) : 0.f);
        den += (__uint_as_float(p0) + __uint_as_float(p1))
             + (__uint_as_float(p2) + __uint_as_float(p3))
             + (__uint_as_float(p4) + __uint_as_float(p5))
             + (__uint_as_float(p6) + __uint_as_float(p7));
        u0.x = p0; u0.y = p4; u0.z = p1; u0.w = p5;   // pairs (c, c+4)
        u1.x = p2; u1.y = p6; u1.z = p3; u1.w = p7;
    };
    auto store_pv = [&](uint32_t pOff) {
        uint32_t* d = (uint32_t*)(sm + pOff + thrWords);
        *(uint4*)d       = u0;
        *(uint4*)(d + 4) = u1;
    };

    // ---- prologue: B(0) via cp.async; adj(0) via direct LDG (one-time) ----
    cp_tileB(0, OFF_SB0);
    asm volatile("cp.async.commit_group;" ::: "memory");
    {
        const int4 a0 = __ldg((const int4*)adjThr);
        const int4 a1 = __ldg((const int4*)adjThr + 1);
        compute_pv(0, a0, a1);
        store_pv(OFF_SA0);
    }
    asm volatile("cp.async.wait_group 0;" ::: "memory");

    float acc[2][4][4];
    #pragma unroll
    for (int mi = 0; mi < 2; mi++)
        #pragma unroll
        for (int ni = 0; ni < 4; ni++)
            #pragma unroll
            for (int q = 0; q < 4; q++) acc[mi][ni][q] = 0.f;

    const int g = lane >> 2, tig = lane & 3;
    const int m0  = (wid & 1) * 32;
    const int nb0 = ((wid >> 1) & 3) * 32;
    const int kh  = wid >> 3;                 // k-split half

    for (int it = 0; it < ITERS; ++it) {
        const int buf = it & 1;
        const uint32_t pOff  = buf ? OFF_SA1 : OFF_SA0;
        const uint32_t bOff  = buf ? OFF_SB1 : OFF_SB0;
        const uint32_t pOffN = buf ? OFF_SA0 : OFF_SA1;

        // one barrier per tile: P[buf] ready; prior MMAs on [buf^1] done
        __syncthreads();

        // issue next tile's copies (B + adj) — land during the MMA block
        if (it + 1 < ITERS) {
            cp_tileB((it + 1) * KT, buf ? OFF_SB0 : OFF_SB1);
            cp_adj((it + 1) * KT, pOffN);
        }
        asm volatile("cp.async.commit_group;" ::: "memory");

        // ---- MMA: acc += P[QT x KT-half] @ Wh[KT-half x 128] ----
        const uint32_t* A = (const uint32_t*)(sm + pOff);
        const uint32_t* B = (const uint32_t*)(sm + bOff);
        #pragma unroll
        for (int ks = 0; ks < 4; ++ks) {
            const int k8 = kh * 4 + ks;
            uint32_t af[2][4];
            #pragma unroll
            for (int mi = 0; mi < 2; mi++) {
                const uint32_t* ap = A + (m0 + 16 * mi + g) * ASTR + k8 * 8 + tig * 2;
                const uint2 pA = *(const uint2*)ap;              // (a0, a2)
                const uint2 pB = *(const uint2*)(ap + 8 * ASTR); // (a1, a3)
                af[mi][0] = pA.x; af[mi][1] = pB.x;
                af[mi][2] = pA.y; af[mi][3] = pB.y;
            }
            uint32_t bf[4][2];
            #pragma unroll
            for (int ni = 0; ni < 4; ni++) {
                const uint2 pb = *(const uint2*)(B + k8 * 1024
                                    + (nb0 + 8 * ni + g) * 8 + tig * 2);
                bf[ni][0] = pb.x; bf[ni][1] = pb.y;
            }
            #pragma unroll
            for (int mi = 0; mi < 2; mi++)
                #pragma unroll
                for (int ni = 0; ni < 4; ni++)
                    mma_tf32(acc[mi][ni], af[mi], bf[ni]);
        }

        // ---- exp for tile it+1: adj now in SMEM (own-thread cp.async) ----
        asm volatile("cp.async.wait_group 0;" ::: "memory");
        if (it + 1 < ITERS) {
            const uint32_t* s = (const uint32_t*)(sm + pOffN + thrWords);
            const int4 a0 = *(const int4*)s;
            const int4 a1 = *(const int4*)(s + 4);
            compute_pv((it + 1) * KT, a0, a1);
            store_pv(pOffN);
        }
    }

    __syncthreads();   // all MMAs done; SMEM reusable

    // ---- denominator: reduce across the 8 threads sharing a row ----
    float* sDen = (float*)(sm + OFF_DEN);
    float dsum = den + __shfl_xor_sync(0xffffffffu, den, 1);
    dsum += __shfl_xor_sync(0xffffffffu, dsum, 2);
    dsum += __shfl_xor_sync(0xffffffffu, dsum, 4);
    if ((t & 7) == 0) sDen[prow] = dsum;

    // ---- k-split merge: kh=1 warps park accs in SMEM (padded stride 36) ----
    float* red = (float*)(sm + OFF_SB0);
    if (kh == 1) {
        float* slot = red + ((size_t)((wid - 8) * 32 + lane)) * 36;
        #pragma unroll
        for (int mi = 0; mi < 2; mi++)
            #pragma unroll
            for (int ni = 0; ni < 4; ni++)
                *(float4*)(slot + (mi * 4 + ni) * 4) = *(float4*)acc[mi][ni];
    }
    __syncthreads();

    if (kh == 0) {
        const float* slot = red + ((size_t)(wid * 32 + lane)) * 36;
        #pragma unroll
        for (int mi = 0; mi < 2; mi++)
            #pragma unroll
            for (int ni = 0; ni < 4; ni++) {
                const float4 v = *(const float4*)(slot + (mi * 4 + ni) * 4);
                acc[mi][ni][0] += v.x; acc[mi][ni][1] += v.y;
                acc[mi][ni][2] += v.z; acc[mi][ni][3] += v.w;
            }

        // ---- epilogue: normalize + ELU, float2 stores ----
        #pragma unroll
        for (int mi = 0; mi < 2; mi++) {
            const int rloc = m0 + 16 * mi + g;
            const int r0 = n0 + rloc;
            const float i0 = 1.0f / sDen[rloc];
            const float i1 = 1.0f / sDen[rloc + 8];
            #pragma unroll
            for (int ni = 0; ni < 4; ni++) {
                const int col = nb0 + 8 * ni + 2 * tig;
                float o0 = acc[mi][ni][0] * i0, o1 = acc[mi][ni][1] * i0;
                float o2 = acc[mi][ni][2] * i1, o3 = acc[mi][ni][3] * i1;
                o0 = (o0 > 0.f) ? o0 : expm1f(o0);
                o1 = (o1 > 0.f) ? o1 : expm1f(o1);
                o2 = (o2 > 0.f) ? o2 : expm1f(o2);
                o3 = (o3 > 0.f) ? o3 : expm1f(o3);
                *(float2*)&out[((size_t)(b * NN) + r0)     * FF + col] = make_float2(o0, o1);
                *(float2*)&out[((size_t)(b * NN) + r0 + 8) * FF + col] = make_float2(o2, o3);
            }
        }
    }
}

// ============================================================================
extern "C" void kernel_launch(void* const* d_in, const int* in_sizes, int n_in,
                              void* d_out, int out_size) {
    const float* h   = (const float*)d_in[0];
    const int*   adj = (const int*)  d_in[1];
    const float* W   = (const float*)d_in[2];
    const float* av  = (const float*)d_in[3];
    float*       out = (float*)d_out;

    cudaFuncSetAttribute(k_wh, cudaFuncAttributeMaxDynamicSharedMemorySize, SMEM_WH);
    k_wh<<<(BB * NN) / 64, 256, SMEM_WH>>>(h, W, av);

    cudaFuncSetAttribute(k_attn, cudaFuncAttributeMaxDynamicSharedMemorySize, SMEM_DYN);
    k_attn<<<BB * (NN / QT), 512, SMEM_DYN>>>(adj, out);
}

// round 14
// speedup vs baseline: 3.7969x; 1.2037x over previous
#include <cuda_runtime.h>
#include <cuda_fp16.h>
#include <math.h>
#include <stdint.h>

#define BB   4
#define NN   4096
#define FIN  256
#define FF   128
#define QT   64                // query rows per block (k_attn)
#define KT   64                // key tile
#define ITERS (NN / KT)
#define LRA  0.2f
#define EXPSH 4.1588831f       // 6*ln2: p = exp(s - 6ln2); cancels in softmax

typedef unsigned long long ull;

// Scratch (device globals: allocation-free rule)
// g_WhH: fp16 Wh in B-fragment-packed layout. ull index:
//   ((b*256 + kb)*128 + f)*4 + tig   holds halves
//   { Wh[16kb+2tig][f], Wh[16kb+2tig+1][f], Wh[16kb+2tig+8][f], Wh[16kb+2tig+9][f] }
__device__ ull   g_WhH[BB * (NN / 16) * FF * 4];   // 4 MB
__device__ float g_Wh1[BB * NN];
__device__ float g_Wh2[BB * NN];

// ---------------------------------------------------------------------------
__device__ __forceinline__ void mma_f16(float* c, const uint32_t* a, const uint32_t* b) {
    asm volatile(
        "mma.sync.aligned.m16n8k16.row.col.f32.f16.f16.f32 "
        "{%0,%1,%2,%3}, {%4,%5,%6,%7}, {%8,%9}, {%0,%1,%2,%3};"
        : "+f"(c[0]), "+f"(c[1]), "+f"(c[2]), "+f"(c[3])
        : "r"(a[0]), "r"(a[1]), "r"(a[2]), "r"(a[3]), "r"(b[0]), "r"(b[1]));
}
__device__ __forceinline__ uint32_t smem_u32(const void* p) {
    uint32_t a;
    asm("{ .reg .u64 t; cvta.to.shared.u64 t, %1; cvt.u32.u64 %0, t; }"
        : "=r"(a) : "l"(p));
    return a;
}
__device__ __forceinline__ void cp16(uint32_t dst, const void* src) {
    asm volatile("cp.async.cg.shared.global [%0], [%1], 16;" :: "r"(dst), "l"(src));
}
__device__ __forceinline__ uint32_t h2pack(float a, float b) {
    const __half2 h = __floats2half2_rn(a, b);
    return *(const uint32_t*)&h;
}
__device__ __forceinline__ float2 h2unpack(uint32_t u) {
    return __half22float2(*(const __half2*)&u);
}
// packed fp32x2 helpers (B300 2x fp32 path)
__device__ __forceinline__ ull ffma2(ull a, ull b, ull c) {
    ull d;
    asm("fma.rn.f32x2 %0, %1, %2, %3;" : "=l"(d) : "l"(a), "l"(b), "l"(c));
    return d;
}
__device__ __forceinline__ ull pack2s(float x) {
    ull p;
    asm("mov.b64 %0, {%1, %2};" : "=l"(p) : "f"(x), "f"(x));
    return p;
}
__device__ __forceinline__ ull packp(float lo, float hi) {
    ull p;
    asm("mov.b64 %0, {%1, %2};" : "=l"(p) : "f"(lo), "f"(hi));
    return p;
}
__device__ __forceinline__ float2 unp2(ull p) {
    float lo, hi;
    asm("mov.b64 {%0, %1}, %2;" : "=f"(lo), "=f"(hi) : "l"(p));
    return make_float2(lo, hi);
}

// ============================================================================
// Kernel 1: Wh = h @ W on packed fma.rn.f32x2.
// 256 threads, 64 rows/block; thread tile 4 rows x 8 cols. Rows assigned as
// {2q, 2q+1, 2q+8, 2q+9} within a 16-row block so the fp16 B-fragment quad
// is a single ull store. Fused Wh1/Wh2 (full fp32) via shuffle reduction.
// ============================================================================
#define SMEM_WH (64 * FIN * 4 + 2 * FF * 4)

__global__ void __launch_bounds__(256, 2)
k_wh(const float* __restrict__ h,
     const float* __restrict__ W,
     const float* __restrict__ av) {
    extern __shared__ char smw[];
    float* sh = (float*)smw;                  // 64 x 256 h tile
    float* sa = sh + 64 * FIN;

    const int t    = threadIdx.x;
    const int row0 = blockIdx.x * 64;

    const float4* src = (const float4*)(h + (size_t)row0 * FIN);
    #pragma unroll
    for (int i = 0; i < 16; i++) ((float4*)sh)[t + i * 256] = src[t + i * 256];
    if (t < 64) ((float4*)sa)[t] = ((const float4*)av)[t];
    __syncthreads();

    const int rg = t >> 4, cg = t & 15;
    const int c0 = cg * 8;
    const int kb = rg >> 2, q = rg & 3;       // 16-row block, quad index
    int rowIdx[4];
    #pragma unroll
    for (int i = 0; i < 4; i++)
        rowIdx[i] = kb * 16 + 2 * q + (i & 1) + 8 * (i >> 1);

    ull acc[4][4];
    #pragma unroll
    for (int i = 0; i < 4; i++)
        #pragma unroll
        for (int j = 0; j < 4; j++) acc[i][j] = 0ull;

    const float4* sh4 = (const float4*)sh;
    #pragma unroll 2
    for (int k0 = 0; k0 < FIN; k0 += 4) {
        float4 hv[4];
        #pragma unroll
        for (int i = 0; i < 4; i++) hv[i] = sh4[rowIdx[i] * 64 + (k0 >> 2)];
        #pragma unroll
        for (int kk = 0; kk < 4; kk++) {
            const float* wr = W + (size_t)(k0 + kk) * FF + c0;
            const float4 wa = *(const float4*)wr;
            const float4 wb = *(const float4*)(wr + 4);
            const ull w0 = packp(wa.x, wa.y), w1 = packp(wa.z, wa.w);
            const ull w2 = packp(wb.x, wb.y), w3 = packp(wb.z, wb.w);
            #pragma unroll
            for (int i = 0; i < 4; i++) {
                const ull aa = pack2s(((const float*)&hv[i])[kk]);
                acc[i][0] = ffma2(aa, w0, acc[i][0]);
                acc[i][1] = ffma2(aa, w1, acc[i][1]);
                acc[i][2] = ffma2(aa, w2, acc[i][2]);
                acc[i][3] = ffma2(aa, w3, acc[i][3]);
            }
        }
    }

    // unpack accs
    float v[4][8];
    #pragma unroll
    for (int i = 0; i < 4; i++)
        #pragma unroll
        for (int j = 0; j < 4; j++) {
            const float2 p = unp2(acc[i][j]);
            v[i][2 * j] = p.x; v[i][2 * j + 1] = p.y;
        }

    // fp16 quad-packed stores: one ull per (f, quad)
    const int bIdx = row0 >> 12;
    const int kbG  = ((row0 & (NN - 1)) >> 4) + kb;
    ull* baseW = g_WhH + ((size_t)(bIdx * 256 + kbG) * 128 + c0) * 4 + q;
    #pragma unroll
    for (int j = 0; j < 8; j++) {
        const uint32_t lo = h2pack(v[0][j], v[1][j]);   // rows 2q, 2q+1
        const uint32_t hi = h2pack(v[2][j], v[3][j]);   // rows 2q+8, 2q+9
        baseW[(size_t)j * 4] = (ull)lo | ((ull)hi << 32);
    }

    // Wh1/Wh2 (full fp32): reduce across the 16 col-threads (half-warp)
    #pragma unroll
    for (int i = 0; i < 4; i++) {
        const int row = row0 + rowIdx[i];
        float p1 = 0.f, p2 = 0.f;
        #pragma unroll
        for (int j = 0; j < 8; j++) {
            p1 += v[i][j] * sa[c0 + j];
            p2 += v[i][j] * sa[FF + c0 + j];
        }
        #pragma unroll
        for (int off = 8; off; off >>= 1) {
            p1 += __shfl_xor_sync(0xffffffffu, p1, off);
            p2 += __shfl_xor_sync(0xffffffffu, p2, off);
        }
        if (cg == 0) { g_Wh1[row] = p1; g_Wh2[row] = p2; }
    }
}

// ============================================================================
// Kernel 2: fused masked-softmax attention, fp16 mma.m16n8k16 (fp32 acc).
// p = exp(lrelu(s) - 6ln2) fits fp16; the 2^-6 cancels in the normalization.
// 512 threads/CTA, 2 CTAs/SM; 16 warps = 2(m32) x 4(n32) x 2(k-split of KT).
// P tile: per (R16, kb) 512B block, layout [h][g][tig] of 4-half quads ->
// A-frags are 2 conflict-free LDS.64; Wh B-frags 1 LDS.64. Single barrier
// per tile; exp(it+1) (direct adj LDG) overlaps MMA(it) across pipes.
// ============================================================================
#define OFF_SA0 0
#define OFF_SA1 8192
#define OFF_SB0 16384
#define OFF_SB1 32768
#define OFF_DEN 49152
#define SMEM_DYN 49408

__global__ void __launch_bounds__(512, 2)
k_attn(const int* __restrict__ adj, float* __restrict__ out) {
    extern __shared__ char sm[];
    const uint32_t sbase = smem_u32(sm);

    const int t = threadIdx.x, lane = t & 31, wid = t >> 5;
    const int b = blockIdx.x >> 6;
    const int n0 = (blockIdx.x & 63) * QT;

    // exp-phase geometry: thread -> (row, kb, half); 8 P values
    const int prow = t >> 3;                 // 0..63
    const int pkb  = (t >> 1) & 3;           // k16 block in tile
    const int phal = t & 1;                  // tig pair {2h, 2h+1}
    const int pR16 = prow >> 4, pH = (prow >> 3) & 1, pG = prow & 7;
    const uint32_t pByte = (uint32_t)((pR16 * 4 + pkb) * 512
                                      + (pH * 32 + pG * 4 + 2 * phal) * 8);
    const float w1 = __ldg(&g_Wh1[b * NN + n0 + prow]);
    const int*   adjThr = adj + (size_t)(b * NN + n0 + prow) * NN + pkb * 16 + phal * 4;
    const float* wh2T   = g_Wh2 + b * NN + pkb * 16 + phal * 4;

    // cp.async Wh fp16 tile: 16KB contiguous (4 kb-blocks)
    auto cp_tileB = [&](int mt, uint32_t bufOff) {
        const char* src = (const char*)(g_WhH + (size_t)(b * 256 + (mt >> 4)) * 128 * 4);
        cp16(sbase + bufOff + (uint32_t)t * 16,          src + (size_t)t * 16);
        cp16(sbase + bufOff + (uint32_t)(t + 512) * 16,  src + (size_t)(t + 512) * 16);
        asm volatile("cp.async.commit_group;" ::: "memory");
    };

    float den = 0.f;

    auto exp_tile = [&](int mt, uint32_t pOff) {
        const int4 aL = __ldg((const int4*)(adjThr + mt));
        const int4 aH = __ldg((const int4*)(adjThr + mt + 8));
        const float4 wL = __ldg((const float4*)(wh2T + mt));
        const float4 wH = __ldg((const float4*)(wh2T + mt + 8));
        float s;
        s = w1 + wL.x; s = fmaxf(s, LRA * s);
        const float pL0 = (aL.x > 0) ? __expf(s - EXPSH) : 0.f;
        s = w1 + wL.y; s = fmaxf(s, LRA * s);
        const float pL1 = (aL.y > 0) ? __expf(s - EXPSH) : 0.f;
        s = w1 + wL.z; s = fmaxf(s, LRA * s);
        const float pL2 = (aL.z > 0) ? __expf(s - EXPSH) : 0.f;
        s = w1 + wL.w; s = fmaxf(s, LRA * s);
        const float pL3 = (aL.w > 0) ? __expf(s - EXPSH) : 0.f;
        s = w1 + wH.x; s = fmaxf(s, LRA * s);
        const float pH0 = (aH.x > 0) ? __expf(s - EXPSH) : 0.f;
        s = w1 + wH.y; s = fmaxf(s, LRA * s);
        const float pH1 = (aH.y > 0) ? __expf(s - EXPSH) : 0.f;
        s = w1 + wH.z; s = fmaxf(s, LRA * s);
        const float pH2 = (aH.z > 0) ? __expf(s - EXPSH) : 0.f;
        s = w1 + wH.w; s = fmaxf(s, LRA * s);
        const float pH3 = (aH.w > 0) ? __expf(s - EXPSH) : 0.f;

        // quads: slot tig0 = {pL0,pL1,pH0,pH1}, slot tig0+1 = {pL2,pL3,pH2,pH3}
        uint4 u;
        u.x = h2pack(pL0, pL1); u.y = h2pack(pH0, pH1);
        u.z = h2pack(pL2, pL3); u.w = h2pack(pH2, pH3);
        // denominator from the ROUNDED values (numerator consistency)
        const float2 r0 = h2unpack(u.x), r1 = h2unpack(u.y);
        const float2 r2 = h2unpack(u.z), r3 = h2unpack(u.w);
        den += (r0.x + r0.y) + (r1.x + r1.y) + (r2.x + r2.y) + (r3.x + r3.y);
        *(uint4*)(sm + pOff + pByte) = u;
    };

    // ---- prologue: tile 0 ----
    cp_tileB(0, OFF_SB0);
    exp_tile(0, OFF_SA0);
    asm volatile("cp.async.wait_group 0;" ::: "memory");

    float acc[2][4][4];
    #pragma unroll
    for (int mi = 0; mi < 2; mi++)
        #pragma unroll
        for (int ni = 0; ni < 4; ni++)
            #pragma unroll
            for (int qq = 0; qq < 4; qq++) acc[mi][ni][qq] = 0.f;

    const int g = lane >> 2, tig = lane & 3;
    const int mR = (wid & 1) * 2;             // R16 base (2 per warp)
    const int nb0 = ((wid >> 1) & 3) * 32;
    const int kh  = wid >> 3;                 // k-split half (2 kb each)

    for (int it = 0; it < ITERS; ++it) {
        const int buf = it & 1;
        const uint32_t pOff  = buf ? OFF_SA1 : OFF_SA0;
        const uint32_t bOff  = buf ? OFF_SB1 : OFF_SB0;
        const uint32_t pOffN = buf ? OFF_SA0 : OFF_SA1;

        // one barrier per tile: P[buf] ready; prior MMAs on [buf^1] done
        __syncthreads();

        if (it + 1 < ITERS) cp_tileB((it + 1) * KT, buf ? OFF_SB0 : OFF_SB1);

        // ---- MMA: acc += P[64 x k32] @ Wh[k32 x 128] ----
        #pragma unroll
        for (int kk = 0; kk < 2; ++kk) {
            const int kb = kh * 2 + kk;
            uint32_t af[2][4];
            #pragma unroll
            for (int mi = 0; mi < 2; mi++) {
                const uint32_t aAddr = pOff + ((mR + mi) * 4 + kb) * 512
                                     + (g * 4 + tig) * 8;
                const uint2 lo = *(const uint2*)(sm + aAddr);        // (a0,a2)
                const uint2 hi = *(const uint2*)(sm + aAddr + 256);  // (a1,a3)
                af[mi][0] = lo.x; af[mi][1] = hi.x;
                af[mi][2] = lo.y; af[mi][3] = hi.y;
            }
            uint32_t bf[4][2];
            #pragma unroll
            for (int ni = 0; ni < 4; ni++) {
                const uint32_t bAddr = bOff
                    + ((kb * 128 + nb0 + 8 * ni + g) * 4 + tig) * 8;
                const uint2 bb = *(const uint2*)(sm + bAddr);
                bf[ni][0] = bb.x; bf[ni][1] = bb.y;
            }
            #pragma unroll
            for (int mi = 0; mi < 2; mi++)
                #pragma unroll
                for (int ni = 0; ni < 4; ni++)
                    mma_f16(acc[mi][ni], af[mi], bf[ni]);
        }

        // ---- exp for tile it+1 (adj via direct LDG; overlaps across warps) ----
        if (it + 1 < ITERS) exp_tile((it + 1) * KT, pOffN);
        asm volatile("cp.async.wait_group 0;" ::: "memory");
    }

    __syncthreads();   // all MMAs done; SMEM reusable

    // ---- denominator: reduce across the 8 threads sharing a row ----
    float* sDen = (float*)(sm + OFF_DEN);
    float dsum = den + __shfl_xor_sync(0xffffffffu, den, 1);
    dsum += __shfl_xor_sync(0xffffffffu, dsum, 2);
    dsum += __shfl_xor_sync(0xffffffffu, dsum, 4);
    if ((t & 7) == 0) sDen[prow] = dsum;

    // ---- k-split merge: kh=1 warps park accs at sm+0 (padded stride 36) ----
    float* red = (float*)sm;
    if (kh == 1) {
        float* slot = red + ((size_t)((wid - 8) * 32 + lane)) * 36;
        #pragma unroll
        for (int mi = 0; mi < 2; mi++)
            #pragma unroll
            for (int ni = 0; ni < 4; ni++)
                *(float4*)(slot + (mi * 4 + ni) * 4) = *(float4*)acc[mi][ni];
    }
    __syncthreads();

    if (kh == 0) {
        const float* slot = red + ((size_t)(wid * 32 + lane)) * 36;
        #pragma unroll
        for (int mi = 0; mi < 2; mi++)
            #pragma unroll
            for (int ni = 0; ni < 4; ni++) {
                const float4 v = *(const float4*)(slot + (mi * 4 + ni) * 4);
                acc[mi][ni][0] += v.x; acc[mi][ni][1] += v.y;
                acc[mi][ni][2] += v.z; acc[mi][ni][3] += v.w;
            }

        // ---- epilogue: normalize + ELU, float2 stores ----
        #pragma unroll
        for (int mi = 0; mi < 2; mi++) {
            const int rloc = (mR + mi) * 16 + g;
            const int r0 = n0 + rloc;
            const float i0 = 1.0f / sDen[rloc];
            const float i1 = 1.0f / sDen[rloc + 8];
            #pragma unroll
            for (int ni = 0; ni < 4; ni++) {
                const int col = nb0 + 8 * ni + 2 * tig;
                float o0 = acc[mi][ni][0] * i0, o1 = acc[mi][ni][1] * i0;
                float o2 = acc[mi][ni][2] * i1, o3 = acc[mi][ni][3] * i1;
                o0 = (o0 > 0.f) ? o0 : expm1f(o0);
                o1 = (o1 > 0.f) ? o1 : expm1f(o1);
                o2 = (o2 > 0.f) ? o2 : expm1f(o2);
                o3 = (o3 > 0.f) ? o3 : expm1f(o3);
                *(float2*)&out[((size_t)(b * NN) + r0)     * FF + col] = make_float2(o0, o1);
                *(float2*)&out[((size_t)(b * NN) + r0 + 8) * FF + col] = make_float2(o2, o3);
            }
        }
    }
}

// ============================================================================
extern "C" void kernel_launch(void* const* d_in, const int* in_sizes, int n_in,
                              void* d_out, int out_size) {
    const float* h   = (const float*)d_in[0];
    const int*   adj = (const int*)  d_in[1];
    const float* W   = (const float*)d_in[2];
    const float* av  = (const float*)d_in[3];
    float*       out = (float*)d_out;

    cudaFuncSetAttribute(k_wh, cudaFuncAttributeMaxDynamicSharedMemorySize, SMEM_WH);
    k_wh<<<(BB * NN) / 64, 256, SMEM_WH>>>(h, W, av);

    cudaFuncSetAttribute(k_attn, cudaFuncAttributeMaxDynamicSharedMemorySize, SMEM_DYN);
    k_attn<<<BB * (NN / QT), 512, SMEM_DYN>>>(adj, out);
}

// round 17
// speedup vs baseline: 4.0034x; 1.0544x over previous
#include <cuda_runtime.h>
#include <cuda_fp16.h>
#include <math.h>
#include <stdint.h>

#define BB   4
#define NN   4096
#define FIN  256
#define FF   128
#define QT   64                // query rows per block (k_attn)
#define KT   64                // key tile
#define ITERS (NN / KT)
#define LRA  0.2f

typedef unsigned long long ull;

// Scratch (device globals: allocation-free rule)
// g_WhH: fp16 Wh in B-fragment-packed layout. ull index:
//   ((b*256 + kb)*128 + f)*4 + tig   holds halves
//   { Wh[16kb+2tig][f], Wh[16kb+2tig+1][f], Wh[16kb+2tig+8][f], Wh[16kb+2tig+9][f] }
__device__ ull   g_WhH[BB * (NN / 16) * FF * 4];   // 4 MB
__device__ float g_Wh1[BB * NN];
__device__ float g_Wh2[BB * NN];

// ---------------------------------------------------------------------------
__device__ __forceinline__ void mma_f16(float* c, const uint32_t* a, const uint32_t* b) {
    asm volatile(
        "mma.sync.aligned.m16n8k16.row.col.f32.f16.f16.f32 "
        "{%0,%1,%2,%3}, {%4,%5,%6,%7}, {%8,%9}, {%0,%1,%2,%3};"
        : "+f"(c[0]), "+f"(c[1]), "+f"(c[2]), "+f"(c[3])
        : "r"(a[0]), "r"(a[1]), "r"(a[2]), "r"(a[3]), "r"(b[0]), "r"(b[1]));
}
__device__ __forceinline__ uint32_t smem_u32(const void* p) {
    uint32_t a;
    asm("{ .reg .u64 t; cvta.to.shared.u64 t, %1; cvt.u32.u64 %0, t; }"
        : "=r"(a) : "l"(p));
    return a;
}
__device__ __forceinline__ void cp16(uint32_t dst, const void* src) {
    asm volatile("cp.async.cg.shared.global [%0], [%1], 16;" :: "r"(dst), "l"(src));
}
__device__ __forceinline__ uint32_t h2pack(float a, float b) {
    const __half2 h = __floats2half2_rn(a, b);
    return *(const uint32_t*)&h;
}
__device__ __forceinline__ float ex2f(float x) {
    float y;
    asm("ex2.approx.f32 %0, %1;" : "=f"(y) : "f"(x));
    return y;
}
// packed fp32x2 helpers (B300 2x fp32 path)
__device__ __forceinline__ ull ffma2(ull a, ull b, ull c) {
    ull d;
    asm("fma.rn.f32x2 %0, %1, %2, %3;" : "=l"(d) : "l"(a), "l"(b), "l"(c));
    return d;
}
__device__ __forceinline__ ull mul2(ull a, ull b) {
    ull d;
    asm("mul.rn.f32x2 %0, %1, %2;" : "=l"(d) : "l"(a), "l"(b));
    return d;
}
__device__ __forceinline__ ull pack2s(float x) {
    ull p;
    asm("mov.b64 %0, {%1, %2};" : "=l"(p) : "f"(x), "f"(x));
    return p;
}
__device__ __forceinline__ ull packp(float lo, float hi) {
    ull p;
    asm("mov.b64 %0, {%1, %2};" : "=l"(p) : "f"(lo), "f"(hi));
    return p;
}
__device__ __forceinline__ float2 unp2(ull p) {
    float lo, hi;
    asm("mov.b64 {%0, %1}, %2;" : "=f"(lo), "=f"(hi) : "l"(p));
    return make_float2(lo, hi);
}

// ============================================================================
// Kernel 1: Wh = h @ W on packed fma.rn.f32x2 (unchanged from R13).
// ============================================================================
#define SMEM_WH (64 * FIN * 4 + 2 * FF * 4)

__global__ void __launch_bounds__(256, 2)
k_wh(const float* __restrict__ h,
     const float* __restrict__ W,
     const float* __restrict__ av) {
    extern __shared__ char smw[];
    float* sh = (float*)smw;                  // 64 x 256 h tile
    float* sa = sh + 64 * FIN;

    const int t    = threadIdx.x;
    const int row0 = blockIdx.x * 64;

    const float4* src = (const float4*)(h + (size_t)row0 * FIN);
    #pragma unroll
    for (int i = 0; i < 16; i++) ((float4*)sh)[t + i * 256] = src[t + i * 256];
    if (t < 64) ((float4*)sa)[t] = ((const float4*)av)[t];
    __syncthreads();

    const int rg = t >> 4, cg = t & 15;
    const int c0 = cg * 8;
    const int kb = rg >> 2, q = rg & 3;       // 16-row block, quad index
    int rowIdx[4];
    #pragma unroll
    for (int i = 0; i < 4; i++)
        rowIdx[i] = kb * 16 + 2 * q + (i & 1) + 8 * (i >> 1);

    ull acc[4][4];
    #pragma unroll
    for (int i = 0; i < 4; i++)
        #pragma unroll
        for (int j = 0; j < 4; j++) acc[i][j] = 0ull;

    const float4* sh4 = (const float4*)sh;
    #pragma unroll 2
    for (int k0 = 0; k0 < FIN; k0 += 4) {
        float4 hv[4];
        #pragma unroll
        for (int i = 0; i < 4; i++) hv[i] = sh4[rowIdx[i] * 64 + (k0 >> 2)];
        #pragma unroll
        for (int kk = 0; kk < 4; kk++) {
            const float* wr = W + (size_t)(k0 + kk) * FF + c0;
            const float4 wa = *(const float4*)wr;
            const float4 wb = *(const float4*)(wr + 4);
            const ull w0 = packp(wa.x, wa.y), w1 = packp(wa.z, wa.w);
            const ull w2 = packp(wb.x, wb.y), w3 = packp(wb.z, wb.w);
            #pragma unroll
            for (int i = 0; i < 4; i++) {
                const ull aa = pack2s(((const float*)&hv[i])[kk]);
                acc[i][0] = ffma2(aa, w0, acc[i][0]);
                acc[i][1] = ffma2(aa, w1, acc[i][1]);
                acc[i][2] = ffma2(aa, w2, acc[i][2]);
                acc[i][3] = ffma2(aa, w3, acc[i][3]);
            }
        }
    }

    // unpack accs
    float v[4][8];
    #pragma unroll
    for (int i = 0; i < 4; i++)
        #pragma unroll
        for (int j = 0; j < 4; j++) {
            const float2 p = unp2(acc[i][j]);
            v[i][2 * j] = p.x; v[i][2 * j + 1] = p.y;
        }

    // fp16 quad-packed stores: one ull per (f, quad)
    const int bIdx = row0 >> 12;
    const int kbG  = ((row0 & (NN - 1)) >> 4) + kb;
    ull* baseW = g_WhH + ((size_t)(bIdx * 256 + kbG) * 128 + c0) * 4 + q;
    #pragma unroll
    for (int j = 0; j < 8; j++) {
        const uint32_t lo = h2pack(v[0][j], v[1][j]);   // rows 2q, 2q+1
        const uint32_t hi = h2pack(v[2][j], v[3][j]);   // rows 2q+8, 2q+9
        baseW[(size_t)j * 4] = (ull)lo | ((ull)hi << 32);
    }

    // Wh1/Wh2 (full fp32): reduce across the 16 col-threads (half-warp)
    #pragma unroll
    for (int i = 0; i < 4; i++) {
        const int row = row0 + rowIdx[i];
        float p1 = 0.f, p2 = 0.f;
        #pragma unroll
        for (int j = 0; j < 8; j++) {
            p1 += v[i][j] * sa[c0 + j];
            p2 += v[i][j] * sa[FF + c0 + j];
        }
        #pragma unroll
        for (int off = 8; off; off >>= 1) {
            p1 += __shfl_xor_sync(0xffffffffu, p1, off);
            p2 += __shfl_xor_sync(0xffffffffu, p2, off);
        }
        if (cg == 0) { g_Wh1[row] = p1; g_Wh2[row] = p2; }
    }
}

// ============================================================================
// Kernel 2: fused masked-softmax attention, fp16 mma.m16n8k16 (fp32 acc).
// p = exp(lrelu(s) - 6ln2) fits fp16; the 2^-6 cancels in the normalization.
// (1) Wh2 for the full key range staged ONCE in SMEM (16KB); (2) adj LDGs
// issued right after the barrier, consumed after the MMA block; (3) exp math
// on packed f32x2; mask via I2F-multiply; den sums pre-rounding fp32.
// FIX vs R15: adj high-quad pointer arithmetic — int + 8 BEFORE the int4
// cast (R15's "(int4*)ap + 1" read cols +4..7 instead of +8..11).
// ============================================================================
#define OFF_SA0 0
#define OFF_SA1 8192
#define OFF_SB0 16384
#define OFF_SB1 32768
#define OFF_W2  49152
#define OFF_DEN 65536
#define SMEM_DYN 65792

__global__ void __launch_bounds__(512, 2)
k_attn(const int* __restrict__ adj, float* __restrict__ out) {
    extern __shared__ char sm[];
    const uint32_t sbase = smem_u32(sm);

    const int t = threadIdx.x, lane = t & 31, wid = t >> 5;
    const int b = blockIdx.x >> 6;
    const int n0 = (blockIdx.x & 63) * QT;

    // exp-phase geometry: thread -> (row, kb, half); 8 P values
    const int prow = t >> 3;                 // 0..63
    const int pkb  = (t >> 1) & 3;           // k16 block in tile
    const int phal = t & 1;                  // tig pair {2h, 2h+1}
    const int pR16 = prow >> 4, pH = (prow >> 3) & 1, pG = prow & 7;
    const uint32_t pByte = (uint32_t)((pR16 * 4 + pkb) * 512
                                      + (pH * 32 + pG * 4 + 2 * phal) * 8);
    const int pk16 = pkb * 16 + phal * 4;    // col offset within tile
    const float w1 = __ldg(&g_Wh1[b * NN + n0 + prow]);
    const int* adjThr = adj + (size_t)(b * NN + n0 + prow) * NN + pk16;

    const ull w1p  = pack2s(w1);
    const ull LRA2 = pack2s(LRA);
    const ull C144 = pack2s(1.44269504f);
    const ull M6   = pack2s(-6.0f);
    const ull ONE2 = pack2s(1.0f);

    // cp.async Wh fp16 tile: 16KB contiguous (4 kb-blocks)
    auto cp_tileB = [&](int mt, uint32_t bufOff) {
        const char* src = (const char*)(g_WhH + (size_t)(b * 256 + (mt >> 4)) * 128 * 4);
        cp16(sbase + bufOff + (uint32_t)t * 16,          src + (size_t)t * 16);
        cp16(sbase + bufOff + (uint32_t)(t + 512) * 16,  src + (size_t)(t + 512) * 16);
    };

    ull den2 = 0ull;

    auto exp_tile = [&](int mt, int4 aL, int4 aH, uint32_t pOff) {
        const float4 wL = *(const float4*)(sm + OFF_W2 + (uint32_t)(mt + pk16) * 4);
        const float4 wH = *(const float4*)(sm + OFF_W2 + (uint32_t)(mt + pk16 + 8) * 4);
        // packed scores s = w1 + w2
        const ull s01 = ffma2(packp(wL.x, wL.y), ONE2, w1p);
        const ull s23 = ffma2(packp(wL.z, wL.w), ONE2, w1p);
        const ull s45 = ffma2(packp(wH.x, wH.y), ONE2, w1p);
        const ull s67 = ffma2(packp(wH.z, wH.w), ONE2, w1p);
        // q = LRA * s (packed), lrelu via scalar fmax on halves
        const float2 sA = unp2(s01), qA = unp2(mul2(s01, LRA2));
        const float2 sB = unp2(s23), qB = unp2(mul2(s23, LRA2));
        const float2 sC = unp2(s45), qC = unp2(mul2(s45, LRA2));
        const float2 sD = unp2(s67), qD = unp2(mul2(s67, LRA2));
        const float l0 = fmaxf(sA.x, qA.x), l1 = fmaxf(sA.y, qA.y);
        const float l2 = fmaxf(sB.x, qB.x), l3 = fmaxf(sB.y, qB.y);
        const float l4 = fmaxf(sC.x, qC.x), l5 = fmaxf(sC.y, qC.y);
        const float l6 = fmaxf(sD.x, qD.x), l7 = fmaxf(sD.y, qD.y);
        // ex2 arg = l*log2e - 6  (== (l - 6ln2)*log2e), packed
        const float2 e01 = unp2(ffma2(packp(l0, l1), C144, M6));
        const float2 e23 = unp2(ffma2(packp(l2, l3), C144, M6));
        const float2 e45 = unp2(ffma2(packp(l4, l5), C144, M6));
        const float2 e67 = unp2(ffma2(packp(l6, l7), C144, M6));
        const float p0 = ex2f(e01.x), p1 = ex2f(e01.y);
        const float p2 = ex2f(e23.x), p3 = ex2f(e23.y);
        const float p4 = ex2f(e45.x), p5 = ex2f(e45.y);
        const float p6 = ex2f(e67.x), p7 = ex2f(e67.y);
        // mask multiply (adj is 0/1) packed
        const ull m01 = mul2(packp(p0, p1),
                             packp(__int2float_rn(aL.x), __int2float_rn(aL.y)));
        const ull m23 = mul2(packp(p2, p3),
                             packp(__int2float_rn(aL.z), __int2float_rn(aL.w)));
        const ull m45 = mul2(packp(p4, p5),
                             packp(__int2float_rn(aH.x), __int2float_rn(aH.y)));
        const ull m67 = mul2(packp(p6, p7),
                             packp(__int2float_rn(aH.z), __int2float_rn(aH.w)));
        // denominator (pre-rounding fp32; consistency error ~1e-5)
        den2 = ffma2(m01, ONE2, den2);
        den2 = ffma2(m23, ONE2, den2);
        den2 = ffma2(m45, ONE2, den2);
        den2 = ffma2(m67, ONE2, den2);
        // fp16 quads (layout: {L01, H01, L23, H23})
        const float2 f01 = unp2(m01), f23 = unp2(m23);
        const float2 f45 = unp2(m45), f67 = unp2(m67);
        uint4 u;
        u.x = h2pack(f01.x, f01.y); u.y = h2pack(f45.x, f45.y);
        u.z = h2pack(f23.x, f23.y); u.w = h2pack(f67.x, f67.y);
        *(uint4*)(sm + pOff + pByte) = u;
    };

    // ---- prologue: stage sWh2 (full key range) + B(0); exp tile 0 ----
    {
        const float* w2src = g_Wh2 + b * NN;
        cp16(sbase + OFF_W2 + (uint32_t)t * 16,         w2src + t * 4);
        cp16(sbase + OFF_W2 + (uint32_t)(t + 512) * 16, w2src + (t + 512) * 4);
        cp_tileB(0, OFF_SB0);
        asm volatile("cp.async.commit_group;" ::: "memory");
        const int4 aL = __ldg((const int4*)adjThr);
        const int4 aH = __ldg((const int4*)(adjThr + 8));       // FIX: +8 ints
        asm volatile("cp.async.wait_group 0;" ::: "memory");
        __syncthreads();                     // sWh2 visible to all threads
        exp_tile(0, aL, aH, OFF_SA0);
    }

    float acc[2][4][4];
    #pragma unroll
    for (int mi = 0; mi < 2; mi++)
        #pragma unroll
        for (int ni = 0; ni < 4; ni++)
            #pragma unroll
            for (int qq = 0; qq < 4; qq++) acc[mi][ni][qq] = 0.f;

    const int g = lane >> 2, tig = lane & 3;
    const int mR = (wid & 1) * 2;             // R16 base (2 per warp)
    const int nb0 = ((wid >> 1) & 3) * 32;
    const int kh  = wid >> 3;                 // k-split half (2 kb each)

    for (int it = 0; it < ITERS; ++it) {
        const int buf = it & 1;
        const uint32_t pOff  = buf ? OFF_SA1 : OFF_SA0;
        const uint32_t bOff  = buf ? OFF_SB1 : OFF_SB0;
        const uint32_t pOffN = buf ? OFF_SA0 : OFF_SA1;

        // one barrier per tile: P[buf] ready; prior MMAs on [buf^1] done
        __syncthreads();

        // early adj loads + next B tile (latency lands under the MMA block)
        int4 aL, aH;
        if (it + 1 < ITERS) {
            const int* ap = adjThr + (it + 1) * KT;
            aL = __ldg((const int4*)ap);
            aH = __ldg((const int4*)(ap + 8));              // FIX: +8 ints
            cp_tileB((it + 1) * KT, buf ? OFF_SB0 : OFF_SB1);
        }
        asm volatile("cp.async.commit_group;" ::: "memory");

        // ---- MMA: acc += P[64 x k32] @ Wh[k32 x 128] ----
        #pragma unroll
        for (int kk = 0; kk < 2; ++kk) {
            const int kb = kh * 2 + kk;
            uint32_t af[2][4];
            #pragma unroll
            for (int mi = 0; mi < 2; mi++) {
                const uint32_t aAddr = pOff + ((mR + mi) * 4 + kb) * 512
                                     + (g * 4 + tig) * 8;
                const uint2 lo = *(const uint2*)(sm + aAddr);        // (a0,a2)
                const uint2 hi = *(const uint2*)(sm + aAddr + 256);  // (a1,a3)
                af[mi][0] = lo.x; af[mi][1] = hi.x;
                af[mi][2] = lo.y; af[mi][3] = hi.y;
            }
            uint32_t bf[4][2];
            #pragma unroll
            for (int ni = 0; ni < 4; ni++) {
                const uint32_t bAddr = bOff
                    + ((kb * 128 + nb0 + 8 * ni + g) * 4 + tig) * 8;
                const uint2 bb = *(const uint2*)(sm + bAddr);
                bf[ni][0] = bb.x; bf[ni][1] = bb.y;
            }
            #pragma unroll
            for (int mi = 0; mi < 2; mi++)
                #pragma unroll
                for (int ni = 0; ni < 4; ni++)
                    mma_f16(acc[mi][ni], af[mi], bf[ni]);
        }

        // ---- exp for tile it+1 (adj already in regs; wh2 from SMEM) ----
        if (it + 1 < ITERS) exp_tile((it + 1) * KT, aL, aH, pOffN);
        asm volatile("cp.async.wait_group 0;" ::: "memory");
    }

    __syncthreads();   // all MMAs done; SMEM reusable

    // ---- denominator: reduce across the 8 threads sharing a row ----
    float* sDen = (float*)(sm + OFF_DEN);
    const float2 dpair = unp2(den2);
    float dsum = dpair.x + dpair.y;
    dsum += __shfl_xor_sync(0xffffffffu, dsum, 1);
    dsum += __shfl_xor_sync(0xffffffffu, dsum, 2);
    dsum += __shfl_xor_sync(0xffffffffu, dsum, 4);
    if ((t & 7) == 0) sDen[prow] = dsum;

    // ---- k-split merge: kh=1 warps park accs at sm+0 (padded stride 36) ----
    float* red = (float*)sm;
    if (kh == 1) {
        float* slot = red + ((size_t)((wid - 8) * 32 + lane)) * 36;
        #pragma unroll
        for (int mi = 0; mi < 2; mi++)
            #pragma unroll
            for (int ni = 0; ni < 4; ni++)
                *(float4*)(slot + (mi * 4 + ni) * 4) = *(float4*)acc[mi][ni];
    }
    __syncthreads();

    if (kh == 0) {
        const float* slot = red + ((size_t)(wid * 32 + lane)) * 36;
        #pragma unroll
        for (int mi = 0; mi < 2; mi++)
            #pragma unroll
            for (int ni = 0; ni < 4; ni++) {
                const float4 v = *(const float4*)(slot + (mi * 4 + ni) * 4);
                acc[mi][ni][0] += v.x; acc[mi][ni][1] += v.y;
                acc[mi][ni][2] += v.z; acc[mi][ni][3] += v.w;
            }

        // ---- epilogue: normalize + ELU, float2 stores ----
        #pragma unroll
        for (int mi = 0; mi < 2; mi++) {
            const int rloc = (mR + mi) * 16 + g;
            const int r0 = n0 + rloc;
            const float i0 = 1.0f / sDen[rloc];
            const float i1 = 1.0f / sDen[rloc + 8];
            #pragma unroll
            for (int ni = 0; ni < 4; ni++) {
                const int col = nb0 + 8 * ni + 2 * tig;
                float o0 = acc[mi][ni][0] * i0, o1 = acc[mi][ni][1] * i0;
                float o2 = acc[mi][ni][2] * i1, o3 = acc[mi][ni][3] * i1;
                o0 = (o0 > 0.f) ? o0 : expm1f(o0);
                o1 = (o1 > 0.f) ? o1 : expm1f(o1);
                o2 = (o2 > 0.f) ? o2 : expm1f(o2);
                o3 = (o3 > 0.f) ? o3 : expm1f(o3);
                *(float2*)&out[((size_t)(b * NN) + r0)     * FF + col] = make_float2(o0, o1);
                *(float2*)&out[((size_t)(b * NN) + r0 + 8) * FF + col] = make_float2(o2, o3);
            }
        }
    }
}

// ============================================================================
extern "C" void kernel_launch(void* const* d_in, const int* in_sizes, int n_in,
                              void* d_out, int out_size) {
    const float* h   = (const float*)d_in[0];
    const int*   adj = (const int*)  d_in[1];
    const float* W   = (const float*)d_in[2];
    const float* av  = (const float*)d_in[3];
    float*       out = (float*)d_out;

    cudaFuncSetAttribute(k_wh, cudaFuncAttributeMaxDynamicSharedMemorySize, SMEM_WH);
    k_wh<<<(BB * NN) / 64, 256, SMEM_WH>>>(h, W, av);

    cudaFuncSetAttribute(k_attn, cudaFuncAttributeMaxDynamicSharedMemorySize, SMEM_DYN);
    k_attn<<<BB * (NN / QT), 512, SMEM_DYN>>>(adj, out);
}